// round 1
// baseline (speedup 1.0000x reference)
#include <cuda_runtime.h>
#include <math.h>

#define B_   2
#define L_   2048
#define H_   1024
#define NH_  4
#define DK_  256
#define DV_  256
#define R_   (B_ * L_)       // 4096 rows
#define NCH_ 64              // chunks of 32 per sequence
#define GIN_ 1056
#define MLPH_ 2048
#define DVS  16              // dv slice width in the scan

// ---------------- scratch (static device memory; no allocations) ----------------
__device__ __align__(128) float g_qp[R_ * H_];     // q proj, later reused as u
__device__ __align__(128) float g_kp[R_ * H_];     // k proj, later reused as w
__device__ __align__(128) float g_vp[R_ * H_];     // v proj, later reused as delta_out
__device__ __align__(128) float g_q[R_ * H_];      // conv+silu q, then l2-normalized in place
__device__ __align__(128) float g_k[R_ * H_];      // conv+silu k, then l2-normalized in place
__device__ __align__(128) float g_v[R_ * H_];      // conv+silu v
__device__ __align__(128) float g_beta[R_ * NH_];
__device__ __align__(128) float g_attn[(size_t)B_ * NH_ * NCH_ * 32 * 32];
__device__ __align__(128) float g_fs[R_ * H_];
__device__ __align__(128) float g_fl[R_ * H_];
__device__ __align__(128) float g_gate[(size_t)R_ * GIN_];
__device__ __align__(128) float g_mlp[(size_t)R_ * MLPH_];
__device__ __align__(128) float g_logits[R_ * 16];
__device__ __align__(128) float g_oc[R_ * H_];

// ---------------- generic fp32 GEMM: C = act(A @ B + bias) ----------------
// A [M,K] rm, B [K,N] rm, C [M,N]. BM=BN=128, BK=16, 256 threads, 8x8 microtile.
// act: 0 = none, 1 = exact gelu
__global__ __launch_bounds__(256) void gemm_f32(
    const float* __restrict__ A, const float* __restrict__ Bm,
    const float* __restrict__ bias, float* __restrict__ C,
    int M, int N, int K, int act)
{
    __shared__ float As[16][128];
    __shared__ float Bs[16][128];
    int tid = threadIdx.x;
    int row0 = blockIdx.y * 128, col0 = blockIdx.x * 128;
    int tr = (tid >> 4) * 8, tc = (tid & 15) * 8;
    float acc[8][8];
#pragma unroll
    for (int i = 0; i < 8; i++)
#pragma unroll
        for (int j = 0; j < 8; j++) acc[i][j] = 0.f;

    for (int k0 = 0; k0 < K; k0 += 16) {
        // load A tile 128x16 (512 float4, 2 per thread), transposed into As
#pragma unroll
        for (int t = tid; t < 512; t += 256) {
            int r = t >> 2, c = (t & 3) * 4;
            float4 av = *(const float4*)(A + (size_t)(row0 + r) * K + k0 + c);
            As[c + 0][r] = av.x; As[c + 1][r] = av.y;
            As[c + 2][r] = av.z; As[c + 3][r] = av.w;
        }
        // load B tile 16x128
#pragma unroll
        for (int t = tid; t < 512; t += 256) {
            int r = t >> 5, c = (t & 31) * 4;
            *(float4*)(&Bs[r][c]) =
                *(const float4*)(Bm + (size_t)(k0 + r) * N + col0 + c);
        }
        __syncthreads();
#pragma unroll
        for (int kk = 0; kk < 16; kk++) {
            float a[8], b[8];
            *(float4*)(a)     = *(const float4*)(&As[kk][tr]);
            *(float4*)(a + 4) = *(const float4*)(&As[kk][tr + 4]);
            *(float4*)(b)     = *(const float4*)(&Bs[kk][tc]);
            *(float4*)(b + 4) = *(const float4*)(&Bs[kk][tc + 4]);
#pragma unroll
            for (int i = 0; i < 8; i++)
#pragma unroll
                for (int j = 0; j < 8; j++) acc[i][j] += a[i] * b[j];
        }
        __syncthreads();
    }
#pragma unroll
    for (int i = 0; i < 8; i++) {
        float out[8];
#pragma unroll
        for (int j = 0; j < 8; j++) {
            float v = acc[i][j];
            if (bias) v += bias[col0 + tc + j];
            if (act == 1) v = 0.5f * v * (1.f + erff(v * 0.70710678118654752f));
            out[j] = v;
        }
        float4* cp = (float4*)(C + (size_t)(row0 + tr + i) * N + col0 + tc);
        cp[0] = *(float4*)(out); cp[1] = *(float4*)(out + 4);
    }
}

// ---------------- beta = sigmoid(x @ Wb), Wb [H,4] ----------------
__global__ void beta_kernel(const float* __restrict__ x, const float* __restrict__ Wb)
{
    int r = blockIdx.x * 4 + (threadIdx.x >> 5);
    int lane = threadIdx.x & 31;
    float acc0 = 0, acc1 = 0, acc2 = 0, acc3 = 0;
    const float* xr = x + (size_t)r * H_;
    for (int kk = lane; kk < H_; kk += 32) {
        float xv = xr[kk];
        const float* w = Wb + kk * 4;
        acc0 += xv * w[0]; acc1 += xv * w[1]; acc2 += xv * w[2]; acc3 += xv * w[3];
    }
#pragma unroll
    for (int off = 16; off; off >>= 1) {
        acc0 += __shfl_down_sync(~0u, acc0, off);
        acc1 += __shfl_down_sync(~0u, acc1, off);
        acc2 += __shfl_down_sync(~0u, acc2, off);
        acc3 += __shfl_down_sync(~0u, acc3, off);
    }
    if (lane == 0) {
        g_beta[r * 4 + 0] = 1.f / (1.f + expf(-acc0));
        g_beta[r * 4 + 1] = 1.f / (1.f + expf(-acc1));
        g_beta[r * 4 + 2] = 1.f / (1.f + expf(-acc2));
        g_beta[r * 4 + 3] = 1.f / (1.f + expf(-acc3));
    }
}

// ---------------- causal depthwise conv K=4 + silu ----------------
__global__ void conv_silu_kernel(const float* __restrict__ src,
                                 const float* __restrict__ w,
                                 float* __restrict__ dst)
{
    int tid = blockIdx.x * blockDim.x + threadIdx.x;   // R_*H_ threads
    int c = tid & (H_ - 1);
    int r = tid >> 10;
    int b = r >> 11;            // L_ = 2048
    int l = r & (L_ - 1);
    const float* wc = w + c * 4;
    float acc = 0.f;
#pragma unroll
    for (int j = 0; j < 4; j++) {
        int ll = l - 3 + j;
        if (ll >= 0) acc += src[((size_t)(b * L_ + ll) << 10) + c] * wc[j];
    }
    dst[tid] = acc / (1.f + expf(-acc));   // silu
}

// ---------------- delta precompute per (b,h,chunk) ----------------
// l2norm q,k; kb=k*beta; vb=v*beta; A=tril(kb k^T,-1); T=inv(I+A) (fwd subst);
// u=T vb; w=T kb; attn=tril(q k^T). qn,kn written in place; u->g_qp, w->g_kp.
#define RS 257
__global__ __launch_bounds__(256) void precomp_kernel()
{
    extern __shared__ float sm[];
    float* Qs = sm;                 // 32*RS
    float* Ks = Qs + 32 * RS;
    float* KB = Ks + 32 * RS;
    float* VB = KB + 32 * RS;
    float* Am = VB + 32 * RS;       // 32*32
    float* Tm = Am + 1024;          // 32*32
    __shared__ float rbeta[32], qn_s[32], kn_s[32];

    int bhn = blockIdx.x;
    int n = bhn % NCH_; int bh = bhn / NCH_;
    int b = bh >> 2, h = bh & 3;
    int l0 = n * 32;
    int tid = threadIdx.x, wi = tid >> 5, lane = tid & 31;

    for (int e = tid; e < 8192; e += 256) {
        int i = e >> 8, d = e & 255;
        size_t gi = ((size_t)(b * L_ + l0 + i) << 10) + h * 256 + d;
        Qs[i * RS + d] = g_q[gi];
        Ks[i * RS + d] = g_k[gi];
    }
    if (tid < 32) rbeta[tid] = g_beta[(b * L_ + l0 + tid) * 4 + h];
    __syncthreads();

    for (int rr = wi; rr < 32; rr += 8) {
        float sq = 0, sk = 0;
        for (int d = lane; d < 256; d += 32) {
            float a = Qs[rr * RS + d]; sq += a * a;
            float c = Ks[rr * RS + d]; sk += c * c;
        }
#pragma unroll
        for (int off = 16; off; off >>= 1) {
            sq += __shfl_down_sync(~0u, sq, off);
            sk += __shfl_down_sync(~0u, sk, off);
        }
        if (lane == 0) { qn_s[rr] = rsqrtf(sq + 1e-6f); kn_s[rr] = rsqrtf(sk + 1e-6f); }
    }
    __syncthreads();

    for (int e = tid; e < 8192; e += 256) {
        int i = e >> 8, d = e & 255;
        size_t gi = ((size_t)(b * L_ + l0 + i) << 10) + h * 256 + d;
        float qv = Qs[i * RS + d] * qn_s[i]; Qs[i * RS + d] = qv;
        float kv = Ks[i * RS + d] * kn_s[i]; Ks[i * RS + d] = kv;
        KB[i * RS + d] = kv * rbeta[i];
        VB[i * RS + d] = g_v[gi] * rbeta[i];
        g_q[gi] = qv; g_k[gi] = kv;
    }
    __syncthreads();

    // A = tril(KB @ Ks^T, -1)
    for (int e = tid; e < 1024; e += 256) {
        int i = e >> 5, j = e & 31;
        float s = 0.f;
        if (j < i) {
            const float* a = KB + i * RS; const float* c = Ks + j * RS;
            for (int d = 0; d < 256; d++) s += a[d] * c[d];
        }
        Am[e] = s;
    }
    __syncthreads();

    // T = inv(I + A): unit lower triangular forward substitution (warp 0, lane = column)
    if (wi == 0) {
        int j = lane;
        for (int i = 0; i < 32; i++) {
            float val = (i == j) ? 1.f : 0.f;
            for (int m = j; m < i; m++) val -= Am[i * 32 + m] * Tm[m * 32 + j];
            Tm[i * 32 + j] = val;
            __syncwarp();
        }
    }
    __syncthreads();

    // attn = tril(Qs @ Ks^T) (with diagonal)
    float* attn_out = g_attn + (((size_t)bh * NCH_ + n) << 10);
    for (int e = tid; e < 1024; e += 256) {
        int i = e >> 5, j = e & 31;
        float s = 0.f;
        if (j <= i) {
            const float* a = Qs + i * RS; const float* c = Ks + j * RS;
            for (int d = 0; d < 256; d++) s += a[d] * c[d];
        }
        attn_out[e] = s;
    }

    // u = T @ VB, w = T @ KB
    for (int e = tid; e < 8192; e += 256) {
        int i = e >> 8, d = e & 255;
        float su = 0, sw = 0;
        const float* tr = Tm + i * 32;
#pragma unroll
        for (int m = 0; m < 32; m++) {
            float t = tr[m];
            su += t * VB[m * RS + d];
            sw += t * KB[m * RS + d];
        }
        size_t gi = ((size_t)(b * L_ + l0 + i) << 10) + h * 256 + d;
        g_qp[gi] = su;   // u
        g_kp[gi] = sw;   // w
    }
}

// ---------------- sequential chunk scan, dv-sliced ----------------
// grid = 8 (b,h) * 16 slices = 128 blocks; S[256][DVS] in smem.
__global__ __launch_bounds__(256) void scan_kernel()
{
    __shared__ float S[256 * DVS];
    __shared__ float U2[32 * DVS];
    __shared__ float At[1024];
    int blk = blockIdx.x;
    int bh = blk >> 4, slice = blk & 15;
    int b = bh >> 2, h = bh & 3;
    int tid = threadIdx.x;
    int dvb = h * 256 + slice * DVS;

    for (int e = tid; e < 256 * DVS; e += 256) S[e] = 0.f;

#pragma unroll 1
    for (int n = 0; n < NCH_; n++) {
        size_t rowbase = ((size_t)(b * L_ + n * 32)) << 10;
        const float* attn_n = g_attn + (((size_t)bh * NCH_ + n) << 10);
        for (int e = tid; e < 1024; e += 256) At[e] = attn_n[e];
        __syncthreads();

        // u2 = u - w @ S
#pragma unroll 1
        for (int e = tid; e < 32 * DVS; e += 256) {
            int i = e / DVS, j = e % DVS;
            const float* wrow = g_kp + rowbase + ((size_t)i << 10) + h * 256;
            float acc = g_qp[rowbase + ((size_t)i << 10) + dvb + j];
#pragma unroll 8
            for (int kk = 0; kk < 256; kk++) acc -= wrow[kk] * S[kk * DVS + j];
            U2[e] = acc;
        }
        __syncthreads();

        // o = q @ S + attn @ u2
#pragma unroll 1
        for (int e = tid; e < 32 * DVS; e += 256) {
            int i = e / DVS, j = e % DVS;
            const float* qrow = g_q + rowbase + ((size_t)i << 10) + h * 256;
            float acc = 0.f;
#pragma unroll 8
            for (int kk = 0; kk < 256; kk++) acc += qrow[kk] * S[kk * DVS + j];
            const float* ar = At + i * 32;
#pragma unroll
            for (int m = 0; m < 32; m++) acc += ar[m] * U2[m * DVS + j];
            g_vp[rowbase + ((size_t)i << 10) + dvb + j] = acc;   // delta_out
        }
        __syncthreads();

        // S += k^T @ u2
#pragma unroll 1
        for (int e = tid; e < 256 * DVS; e += 256) {
            int kk = e / DVS, j = e % DVS;
            float acc = S[e];
#pragma unroll
            for (int i = 0; i < 32; i++)
                acc += g_k[rowbase + ((size_t)i << 10) + h * 256 + kk] * U2[i * DVS + j];
            S[e] = acc;
        }
        __syncthreads();
    }
}

// ---------------- FIR convs (K=3 and K=63) over v, tiled ----------------
__global__ __launch_bounds__(256) void fir_kernel(const float* __restrict__ ws,
                                                  const float* __restrict__ wl)
{
    __shared__ float vt[94][64];       // 32+62 rows
    __shared__ float wls[64 * 63];
    __shared__ float wss[64 * 3];
    int cb = blockIdx.x;               // 16
    int lb = blockIdx.y;               // 128 = B * 64
    int b = lb >> 6;
    int l0 = (lb & 63) * 32;
    int c0 = cb * 64;
    int tid = threadIdx.x;

    for (int e = tid; e < 94 * 64; e += 256) {
        int rr = e >> 6, cc = e & 63;
        int l = l0 - 62 + rr;
        vt[rr][cc] = (l >= 0) ? g_v[((size_t)(b * L_ + l) << 10) + c0 + cc] : 0.f;
    }
    for (int e = tid; e < 64 * 63; e += 256) wls[e] = wl[(size_t)c0 * 63 + e];
    for (int e = tid; e < 64 * 3; e += 256)  wss[e] = ws[(size_t)c0 * 3 + e];
    __syncthreads();

    for (int e = tid; e < 32 * 64; e += 256) {
        int i = e >> 6, cc = e & 63;
        float aL = 0.f, aS = 0.f;
        const float* wlr = wls + cc * 63;
#pragma unroll 9
        for (int j = 0; j < 63; j++) aL += vt[i + j][cc] * wlr[j];
        const float* wsr = wss + cc * 3;
#pragma unroll
        for (int j = 0; j < 3; j++) aS += vt[i + 60 + j][cc] * wsr[j];
        size_t gi = ((size_t)(b * L_ + l0 + i) << 10) + c0 + cc;
        g_fl[gi] = aL;
        g_fs[gi] = aS;
    }
}

// ---------------- gate input assembly: [x | stats(fs,fl,delta,v)] ----------------
__global__ void gate_kernel(const float* __restrict__ x)
{
    int r = blockIdx.x, tid = threadIdx.x;
    float* grow = g_gate + (size_t)r * GIN_;
    const float* xr = x + (size_t)r * H_;
    for (int e = tid; e < H_; e += 256) grow[e] = xr[e];

    int wi = tid >> 5, lane = tid & 31;
    for (int p = wi; p < 16; p += 8) {
        int br = p >> 2, h = p & 3;
        const float* src = (br == 0 ? g_fs : br == 1 ? g_fl : br == 2 ? g_vp : g_v)
                           + ((size_t)r << 10) + h * 256;
        float s = 0, s2 = 0;
        for (int d = lane; d < 256; d += 32) { float t = src[d]; s += t; s2 += t * t; }
#pragma unroll
        for (int off = 16; off; off >>= 1) {
            s += __shfl_down_sync(~0u, s, off);
            s2 += __shfl_down_sync(~0u, s2, off);
        }
        if (lane == 0) {
            float mean = s * (1.f / 256.f);
            float var = s2 * (1.f / 256.f) - mean * mean;
            grow[1024 + br * 8 + h] = mean;
            grow[1024 + br * 8 + 4 + h] = sqrtf(fmaxf(var, 1e-6f));
        }
    }
}

// ---------------- MLP second layer: logits = h @ w2 + b2, N=16 ----------------
__global__ void mlp2_kernel(const float* __restrict__ w2, const float* __restrict__ b2)
{
    int r = blockIdx.x, tid = threadIdx.x;  // 128 threads
    float acc[16];
#pragma unroll
    for (int o = 0; o < 16; o++) acc[o] = 0.f;
    const float* hr = g_mlp + (size_t)r * MLPH_;
    for (int kk = tid; kk < MLPH_; kk += 128) {
        float hv = hr[kk];
        const float4* wr = (const float4*)(w2 + (size_t)kk * 16);
        float4 w0 = wr[0], w1 = wr[1], w2v = wr[2], w3 = wr[3];
        acc[0] += hv * w0.x; acc[1] += hv * w0.y; acc[2] += hv * w0.z; acc[3] += hv * w0.w;
        acc[4] += hv * w1.x; acc[5] += hv * w1.y; acc[6] += hv * w1.z; acc[7] += hv * w1.w;
        acc[8] += hv * w2v.x; acc[9] += hv * w2v.y; acc[10] += hv * w2v.z; acc[11] += hv * w2v.w;
        acc[12] += hv * w3.x; acc[13] += hv * w3.y; acc[14] += hv * w3.z; acc[15] += hv * w3.w;
    }
    __shared__ float part[4][16];
    int wi = tid >> 5, lane = tid & 31;
#pragma unroll
    for (int o = 0; o < 16; o++) {
        float v = acc[o];
#pragma unroll
        for (int off = 16; off; off >>= 1) v += __shfl_down_sync(~0u, v, off);
        if (lane == 0) part[wi][o] = v;
    }
    __syncthreads();
    if (tid < 16)
        g_logits[r * 16 + tid] =
            part[0][tid] + part[1][tid] + part[2][tid] + part[3][tid] + b2[tid];
}

// ---------------- softmax gate, combine branches, RMSNorm ----------------
__global__ void combine_kernel(const float* __restrict__ ltemp,
                               const float* __restrict__ onw)
{
    int r = blockIdx.x, tid = threadIdx.x;   // 256 threads, tid = d
    __shared__ float red[256];
    const float* lg = g_logits + r * 16;
#pragma unroll 1
    for (int h = 0; h < 4; h++) {
        float temp = log1pf(expf(ltemp[h])) + 1e-4f;
        float l0 = lg[h * 4 + 0] / temp, l1 = lg[h * 4 + 1] / temp;
        float l2 = lg[h * 4 + 2] / temp, l3 = lg[h * 4 + 3] / temp;
        float mx = fmaxf(fmaxf(l0, l1), fmaxf(l2, l3));
        float e0 = expf(l0 - mx), e1 = expf(l1 - mx), e2 = expf(l2 - mx), e3 = expf(l3 - mx);
        float inv = 1.f / (e0 + e1 + e2 + e3);
        size_t idx = ((size_t)r << 10) + h * 256 + tid;
        float ov = (e0 * g_fs[idx] + e1 * g_fl[idx] + e2 * g_vp[idx] + e3 * g_v[idx]) * inv;
        red[tid] = ov * ov;
        __syncthreads();
        for (int s = 128; s; s >>= 1) { if (tid < s) red[tid] += red[tid + s]; __syncthreads(); }
        float scale = rsqrtf(red[0] * (1.f / 256.f) + 1e-5f);
        g_oc[idx] = ov * scale * onw[tid];
        __syncthreads();
    }
}

// ---------------- launch ----------------
extern "C" void kernel_launch(void* const* d_in, const int* in_sizes, int n_in,
                              void* d_out, int out_size)
{
    const float* x   = (const float*)d_in[0];
    const float* Wq  = (const float*)d_in[1];
    const float* Wk  = (const float*)d_in[2];
    const float* Wv  = (const float*)d_in[3];
    const float* Wb  = (const float*)d_in[4];
    const float* cq  = (const float*)d_in[5];
    const float* ck  = (const float*)d_in[6];
    const float* cv  = (const float*)d_in[7];
    const float* fsw = (const float*)d_in[8];
    const float* flw = (const float*)d_in[9];
    const float* w1  = (const float*)d_in[10];
    const float* b1  = (const float*)d_in[11];
    const float* w2  = (const float*)d_in[12];
    const float* b2  = (const float*)d_in[13];
    const float* lt  = (const float*)d_in[14];
    const float* onw = (const float*)d_in[15];
    const float* Wo  = (const float*)d_in[16];
    float* out = (float*)d_out;

    void* p;
    float *qp, *kp, *vp, *qq, *kk_, *vv, *gate, *mlp, *oc;
    cudaGetSymbolAddress(&p, g_qp);  qp = (float*)p;
    cudaGetSymbolAddress(&p, g_kp);  kp = (float*)p;
    cudaGetSymbolAddress(&p, g_vp);  vp = (float*)p;
    cudaGetSymbolAddress(&p, g_q);   qq = (float*)p;
    cudaGetSymbolAddress(&p, g_k);   kk_ = (float*)p;
    cudaGetSymbolAddress(&p, g_v);   vv = (float*)p;
    cudaGetSymbolAddress(&p, g_gate); gate = (float*)p;
    cudaGetSymbolAddress(&p, g_mlp); mlp = (float*)p;
    cudaGetSymbolAddress(&p, g_oc);  oc = (float*)p;

    dim3 thr(256);
    // 1. projections
    gemm_f32<<<dim3(H_ / 128, R_ / 128), thr>>>(x, Wq, nullptr, qp, R_, H_, H_, 0);
    gemm_f32<<<dim3(H_ / 128, R_ / 128), thr>>>(x, Wk, nullptr, kp, R_, H_, H_, 0);
    gemm_f32<<<dim3(H_ / 128, R_ / 128), thr>>>(x, Wv, nullptr, vp, R_, H_, H_, 0);
    beta_kernel<<<R_ / 4, 128>>>(x, Wb);
    // 2. short convs + silu
    conv_silu_kernel<<<R_ * H_ / 256, thr>>>(qp, cq, qq);
    conv_silu_kernel<<<R_ * H_ / 256, thr>>>(kp, ck, kk_);
    conv_silu_kernel<<<R_ * H_ / 256, thr>>>(vp, cv, vv);
    // 3. delta precompute (u -> g_qp, w -> g_kp; qn/kn in place)
    size_t smemP = (size_t)(4 * 32 * RS + 2048) * sizeof(float);
    cudaFuncSetAttribute(precomp_kernel, cudaFuncAttributeMaxDynamicSharedMemorySize, (int)smemP);
    precomp_kernel<<<B_ * NH_ * NCH_, thr, smemP>>>();
    // 4. sequential scan (delta_out -> g_vp)
    scan_kernel<<<B_ * NH_ * (DV_ / DVS), thr>>>();
    // 5. FIR convs
    fir_kernel<<<dim3(H_ / 64, B_ * L_ / 32), thr>>>(fsw, flw);
    // 6. gate input
    gate_kernel<<<R_, thr>>>(x);
    // 7. MLP
    gemm_f32<<<dim3(MLPH_ / 128, R_ / 128), thr>>>(gate, w1, b1, mlp, R_, MLPH_, GIN_, 1);
    mlp2_kernel<<<R_, 128>>>(w2, b2);
    // 8. combine + RMSNorm
    combine_kernel<<<R_, thr>>>(lt, onw);
    // 9. output projection
    gemm_f32<<<dim3(H_ / 128, R_ / 128), thr>>>(oc, Wo, nullptr, out, R_, H_, H_, 0);
}

// round 3
// speedup vs baseline: 1.1463x; 1.1463x over previous
#include <cuda_runtime.h>
#include <cuda_bf16.h>
#include <stdint.h>
#include <math.h>

#define B_   2
#define L_   2048
#define H_   1024
#define NH_  4
#define DK_  256
#define DV_  256
#define R_   (B_ * L_)       // 4096 rows
#define NCH_ 64              // chunks of 32 per sequence
#define GIN_ 1056
#define MLPH_ 2048
#define DVS  16              // dv slice width in the scan

// ---------------- scratch (static device memory; no allocations) ----------------
__device__ __align__(128) float g_qp[R_ * H_];     // q proj, later reused as u
__device__ __align__(128) float g_kp[R_ * H_];     // k proj, later reused as w
__device__ __align__(128) float g_vp[R_ * H_];     // v proj, later reused as delta_out
__device__ __align__(128) float g_q[R_ * H_];      // conv+silu q, then l2-normalized in place
__device__ __align__(128) float g_k[R_ * H_];      // conv+silu k, then l2-normalized in place
__device__ __align__(128) float g_v[R_ * H_];      // conv+silu v
__device__ __align__(128) float g_beta[R_ * NH_];
__device__ __align__(128) float g_attn[(size_t)B_ * NH_ * NCH_ * 32 * 32];
__device__ __align__(128) float g_fs[R_ * H_];
__device__ __align__(128) float g_fl[R_ * H_];
__device__ __align__(128) float g_gate[(size_t)R_ * GIN_];
__device__ __align__(128) float g_mlp[(size_t)R_ * MLPH_];
__device__ __align__(128) float g_logits[R_ * 16];
__device__ __align__(128) float g_oc[R_ * H_];

// bf16 split weights, transposed to [N][K]
__device__ __align__(128) __nv_bfloat16 g_wqh[H_ * H_], g_wql[H_ * H_];
__device__ __align__(128) __nv_bfloat16 g_wkh[H_ * H_], g_wkl[H_ * H_];
__device__ __align__(128) __nv_bfloat16 g_wvh[H_ * H_], g_wvl[H_ * H_];
__device__ __align__(128) __nv_bfloat16 g_w1h[MLPH_ * GIN_], g_w1l[MLPH_ * GIN_];
__device__ __align__(128) __nv_bfloat16 g_woh[H_ * H_], g_wol[H_ * H_];

// ---------------- weight transpose + bf16 hi/lo split ----------------
// W [K][N] fp32 -> Th/Tl [N][K] bf16
__global__ void wconv_kernel(const float* __restrict__ W,
                             __nv_bfloat16* __restrict__ Th,
                             __nv_bfloat16* __restrict__ Tl, int K, int N)
{
    __shared__ float t[32][33];
    int k0 = blockIdx.y * 32, n0 = blockIdx.x * 32;
    int tx = threadIdx.x, ty = threadIdx.y;   // 32 x 8
    for (int i = ty; i < 32; i += 8)
        t[i][tx] = W[(size_t)(k0 + i) * N + n0 + tx];
    __syncthreads();
    for (int i = ty; i < 32; i += 8) {
        float v = t[tx][i];                   // = W[k0+tx][n0+i]
        __nv_bfloat16 hi = __float2bfloat16(v);
        __nv_bfloat16 lo = __float2bfloat16(v - __bfloat162float(hi));
        size_t o = (size_t)(n0 + i) * K + k0 + tx;
        Th[o] = hi; Tl[o] = lo;
    }
}

// ---------------- tensor-core GEMM: C = act(A @ B + bias) ----------------
// A [M,K] fp32 row-major (split to bf16 hi/lo on the fly)
// B given pre-split/transposed: Bh/Bl [N][K] bf16
// 3-pass split: Ah*Bh + Al*Bh + Ah*Bl, fp32 accumulate.
// BM=BN=128, BK=16, 256 threads = 8 warps (4m x 2n), warp tile 32x64.
#define MMA16816(d, a, b0, b1) \
  asm volatile("mma.sync.aligned.m16n8k16.row.col.f32.bf16.bf16.f32 " \
    "{%0,%1,%2,%3}, {%4,%5,%6,%7}, {%8,%9}, {%0,%1,%2,%3};" \
    : "+f"(d[0]), "+f"(d[1]), "+f"(d[2]), "+f"(d[3]) \
    : "r"(a[0]), "r"(a[1]), "r"(a[2]), "r"(a[3]), "r"(b0), "r"(b1))

#define ASTRIDE 24   // bf16 row stride in smem

__global__ __launch_bounds__(256) void gemm_tc(
    const float* __restrict__ A,
    const __nv_bfloat16* __restrict__ Bhg, const __nv_bfloat16* __restrict__ Blg,
    const float* __restrict__ bias, float* __restrict__ C,
    int M, int N, int K, int act)
{
    __shared__ __nv_bfloat16 Ah[128 * ASTRIDE], Al[128 * ASTRIDE];
    __shared__ __nv_bfloat16 Bh[128 * ASTRIDE], Bl[128 * ASTRIDE];
    int tid = threadIdx.x;
    int row0 = blockIdx.y * 128, col0 = blockIdx.x * 128;
    int wid = tid >> 5, lane = tid & 31;
    int wm = (wid >> 1) * 32, wn = (wid & 1) * 64;
    int g = lane >> 2, t = lane & 3;

    float acc[2][8][4];
#pragma unroll
    for (int i = 0; i < 2; i++)
#pragma unroll
        for (int j = 0; j < 8; j++)
#pragma unroll
            for (int q = 0; q < 4; q++) acc[i][j][q] = 0.f;

    int arow = tid >> 2, ac4 = (tid & 3) * 4;      // A: 2 float4 per thread
    int brow = tid >> 1, bp = (tid & 1) * 8;       // B: 1 uint4 per matrix half-row

    for (int k0 = 0; k0 < K; k0 += 16) {
#pragma unroll
        for (int s = 0; s < 2; s++) {
            int r = arow + s * 64;
            float4 av = *(const float4*)(A + (size_t)(row0 + r) * K + k0 + ac4);
            __nv_bfloat162 h01 = __float22bfloat162_rn(make_float2(av.x, av.y));
            __nv_bfloat162 h23 = __float22bfloat162_rn(make_float2(av.z, av.w));
            float lx = av.x - __low2float(h01),  ly = av.y - __high2float(h01);
            float lz = av.z - __low2float(h23),  lw = av.w - __high2float(h23);
            __nv_bfloat162 l01 = __float22bfloat162_rn(make_float2(lx, ly));
            __nv_bfloat162 l23 = __float22bfloat162_rn(make_float2(lz, lw));
            *(__nv_bfloat162*)&Ah[r * ASTRIDE + ac4]     = h01;
            *(__nv_bfloat162*)&Ah[r * ASTRIDE + ac4 + 2] = h23;
            *(__nv_bfloat162*)&Al[r * ASTRIDE + ac4]     = l01;
            *(__nv_bfloat162*)&Al[r * ASTRIDE + ac4 + 2] = l23;
        }
        *(uint4*)&Bh[brow * ASTRIDE + bp] =
            *(const uint4*)(Bhg + (size_t)(col0 + brow) * K + k0 + bp);
        *(uint4*)&Bl[brow * ASTRIDE + bp] =
            *(const uint4*)(Blg + (size_t)(col0 + brow) * K + k0 + bp);
        __syncthreads();

        uint32_t afh[2][4], afl[2][4];
#pragma unroll
        for (int mi = 0; mi < 2; mi++) {
            int mb = wm + mi * 16;
            afh[mi][0] = *(const uint32_t*)&Ah[(mb + g)     * ASTRIDE + 2 * t];
            afh[mi][1] = *(const uint32_t*)&Ah[(mb + 8 + g) * ASTRIDE + 2 * t];
            afh[mi][2] = *(const uint32_t*)&Ah[(mb + g)     * ASTRIDE + 2 * t + 8];
            afh[mi][3] = *(const uint32_t*)&Ah[(mb + 8 + g) * ASTRIDE + 2 * t + 8];
            afl[mi][0] = *(const uint32_t*)&Al[(mb + g)     * ASTRIDE + 2 * t];
            afl[mi][1] = *(const uint32_t*)&Al[(mb + 8 + g) * ASTRIDE + 2 * t];
            afl[mi][2] = *(const uint32_t*)&Al[(mb + g)     * ASTRIDE + 2 * t + 8];
            afl[mi][3] = *(const uint32_t*)&Al[(mb + 8 + g) * ASTRIDE + 2 * t + 8];
        }
#pragma unroll
        for (int ni = 0; ni < 8; ni++) {
            int nb = wn + ni * 8;
            uint32_t bh0 = *(const uint32_t*)&Bh[(nb + g) * ASTRIDE + 2 * t];
            uint32_t bh1 = *(const uint32_t*)&Bh[(nb + g) * ASTRIDE + 2 * t + 8];
            uint32_t bl0 = *(const uint32_t*)&Bl[(nb + g) * ASTRIDE + 2 * t];
            uint32_t bl1 = *(const uint32_t*)&Bl[(nb + g) * ASTRIDE + 2 * t + 8];
#pragma unroll
            for (int mi = 0; mi < 2; mi++) {
                MMA16816(acc[mi][ni], afh[mi], bh0, bh1);
                MMA16816(acc[mi][ni], afl[mi], bh0, bh1);
                MMA16816(acc[mi][ni], afh[mi], bl0, bl1);
            }
        }
        __syncthreads();
    }

#pragma unroll
    for (int mi = 0; mi < 2; mi++)
#pragma unroll
        for (int ni = 0; ni < 8; ni++) {
            int r = row0 + wm + mi * 16 + g;
            int c = col0 + wn + ni * 8 + 2 * t;
            float v[4];
#pragma unroll
            for (int q = 0; q < 4; q++) {
                float x = acc[mi][ni][q];
                if (bias) x += bias[c + (q & 1)];
                if (act == 1) x = 0.5f * x * (1.f + erff(x * 0.70710678118654752f));
                v[q] = x;
            }
            *(float2*)(C + (size_t)r * N + c)       = make_float2(v[0], v[1]);
            *(float2*)(C + (size_t)(r + 8) * N + c) = make_float2(v[2], v[3]);
        }
}

// ---------------- beta = sigmoid(x @ Wb), Wb [H,4] ----------------
__global__ void beta_kernel(const float* __restrict__ x, const float* __restrict__ Wb)
{
    int r = blockIdx.x * 4 + (threadIdx.x >> 5);
    int lane = threadIdx.x & 31;
    float acc0 = 0, acc1 = 0, acc2 = 0, acc3 = 0;
    const float* xr = x + (size_t)r * H_;
    for (int kk = lane; kk < H_; kk += 32) {
        float xv = xr[kk];
        const float* w = Wb + kk * 4;
        acc0 += xv * w[0]; acc1 += xv * w[1]; acc2 += xv * w[2]; acc3 += xv * w[3];
    }
#pragma unroll
    for (int off = 16; off; off >>= 1) {
        acc0 += __shfl_down_sync(~0u, acc0, off);
        acc1 += __shfl_down_sync(~0u, acc1, off);
        acc2 += __shfl_down_sync(~0u, acc2, off);
        acc3 += __shfl_down_sync(~0u, acc3, off);
    }
    if (lane == 0) {
        g_beta[r * 4 + 0] = 1.f / (1.f + expf(-acc0));
        g_beta[r * 4 + 1] = 1.f / (1.f + expf(-acc1));
        g_beta[r * 4 + 2] = 1.f / (1.f + expf(-acc2));
        g_beta[r * 4 + 3] = 1.f / (1.f + expf(-acc3));
    }
}

// ---------------- causal depthwise conv K=4 + silu ----------------
__global__ void conv_silu_kernel(const float* __restrict__ src,
                                 const float* __restrict__ w,
                                 float* __restrict__ dst)
{
    int tid = blockIdx.x * blockDim.x + threadIdx.x;   // R_*H_ threads
    int c = tid & (H_ - 1);
    int r = tid >> 10;
    int b = r >> 11;            // L_ = 2048
    int l = r & (L_ - 1);
    const float* wc = w + c * 4;
    float acc = 0.f;
#pragma unroll
    for (int j = 0; j < 4; j++) {
        int ll = l - 3 + j;
        if (ll >= 0) acc += src[((size_t)(b * L_ + ll) << 10) + c] * wc[j];
    }
    dst[tid] = acc / (1.f + expf(-acc));   // silu
}

// ---------------- delta precompute per (b,h,chunk) ----------------
#define RS 257
__global__ __launch_bounds__(256) void precomp_kernel()
{
    extern __shared__ float sm[];
    float* Qs = sm;                 // 32*RS
    float* Ks = Qs + 32 * RS;
    float* KB = Ks + 32 * RS;
    float* VB = KB + 32 * RS;
    float* Am = VB + 32 * RS;       // 32*32
    float* Tm = Am + 1024;          // 32*32
    __shared__ float rbeta[32], qn_s[32], kn_s[32];

    int bhn = blockIdx.x;
    int n = bhn % NCH_; int bh = bhn / NCH_;
    int b = bh >> 2, h = bh & 3;
    int l0 = n * 32;
    int tid = threadIdx.x, wi = tid >> 5, lane = tid & 31;

    for (int e = tid; e < 8192; e += 256) {
        int i = e >> 8, d = e & 255;
        size_t gi = ((size_t)(b * L_ + l0 + i) << 10) + h * 256 + d;
        Qs[i * RS + d] = g_q[gi];
        Ks[i * RS + d] = g_k[gi];
    }
    if (tid < 32) rbeta[tid] = g_beta[(b * L_ + l0 + tid) * 4 + h];
    __syncthreads();

    for (int rr = wi; rr < 32; rr += 8) {
        float sq = 0, sk = 0;
        for (int d = lane; d < 256; d += 32) {
            float a = Qs[rr * RS + d]; sq += a * a;
            float c = Ks[rr * RS + d]; sk += c * c;
        }
#pragma unroll
        for (int off = 16; off; off >>= 1) {
            sq += __shfl_down_sync(~0u, sq, off);
            sk += __shfl_down_sync(~0u, sk, off);
        }
        if (lane == 0) { qn_s[rr] = rsqrtf(sq + 1e-6f); kn_s[rr] = rsqrtf(sk + 1e-6f); }
    }
    __syncthreads();

    for (int e = tid; e < 8192; e += 256) {
        int i = e >> 8, d = e & 255;
        size_t gi = ((size_t)(b * L_ + l0 + i) << 10) + h * 256 + d;
        float qv = Qs[i * RS + d] * qn_s[i]; Qs[i * RS + d] = qv;
        float kv = Ks[i * RS + d] * kn_s[i]; Ks[i * RS + d] = kv;
        KB[i * RS + d] = kv * rbeta[i];
        VB[i * RS + d] = g_v[gi] * rbeta[i];
        g_q[gi] = qv; g_k[gi] = kv;
    }
    __syncthreads();

    // A = tril(KB @ Ks^T, -1)
    for (int e = tid; e < 1024; e += 256) {
        int i = e >> 5, j = e & 31;
        float s = 0.f;
        if (j < i) {
            const float* a = KB + i * RS; const float* c = Ks + j * RS;
            for (int d = 0; d < 256; d++) s += a[d] * c[d];
        }
        Am[e] = s;
    }
    __syncthreads();

    // T = inv(I + A): unit lower triangular forward substitution
    if (wi == 0) {
        int j = lane;
        for (int i = 0; i < 32; i++) {
            float val = (i == j) ? 1.f : 0.f;
            for (int m = j; m < i; m++) val -= Am[i * 32 + m] * Tm[m * 32 + j];
            Tm[i * 32 + j] = val;
            __syncwarp();
        }
    }
    __syncthreads();

    // attn = tril(Qs @ Ks^T) (with diagonal)
    float* attn_out = g_attn + (((size_t)bh * NCH_ + n) << 10);
    for (int e = tid; e < 1024; e += 256) {
        int i = e >> 5, j = e & 31;
        float s = 0.f;
        if (j <= i) {
            const float* a = Qs + i * RS; const float* c = Ks + j * RS;
            for (int d = 0; d < 256; d++) s += a[d] * c[d];
        }
        attn_out[e] = s;
    }

    // u = T @ VB, w = T @ KB
    for (int e = tid; e < 8192; e += 256) {
        int i = e >> 8, d = e & 255;
        float su = 0, sw = 0;
        const float* tr = Tm + i * 32;
#pragma unroll
        for (int m = 0; m < 32; m++) {
            float t = tr[m];
            su += t * VB[m * RS + d];
            sw += t * KB[m * RS + d];
        }
        size_t gi = ((size_t)(b * L_ + l0 + i) << 10) + h * 256 + d;
        g_qp[gi] = su;   // u
        g_kp[gi] = sw;   // w
    }
}

// ---------------- sequential chunk scan, dv-sliced ----------------
__global__ __launch_bounds__(256) void scan_kernel()
{
    __shared__ float S[256 * DVS];
    __shared__ float U2[32 * DVS];
    __shared__ float At[1024];
    int blk = blockIdx.x;
    int bh = blk >> 4, slice = blk & 15;
    int b = bh >> 2, h = bh & 3;
    int tid = threadIdx.x;
    int dvb = h * 256 + slice * DVS;

    for (int e = tid; e < 256 * DVS; e += 256) S[e] = 0.f;

#pragma unroll 1
    for (int n = 0; n < NCH_; n++) {
        size_t rowbase = ((size_t)(b * L_ + n * 32)) << 10;
        const float* attn_n = g_attn + (((size_t)bh * NCH_ + n) << 10);
        for (int e = tid; e < 1024; e += 256) At[e] = attn_n[e];
        __syncthreads();

        // u2 = u - w @ S
#pragma unroll 1
        for (int e = tid; e < 32 * DVS; e += 256) {
            int i = e / DVS, j = e % DVS;
            const float* wrow = g_kp + rowbase + ((size_t)i << 10) + h * 256;
            float acc = g_qp[rowbase + ((size_t)i << 10) + dvb + j];
#pragma unroll 8
            for (int kk = 0; kk < 256; kk++) acc -= wrow[kk] * S[kk * DVS + j];
            U2[e] = acc;
        }
        __syncthreads();

        // o = q @ S + attn @ u2
#pragma unroll 1
        for (int e = tid; e < 32 * DVS; e += 256) {
            int i = e / DVS, j = e % DVS;
            const float* qrow = g_q + rowbase + ((size_t)i << 10) + h * 256;
            float acc = 0.f;
#pragma unroll 8
            for (int kk = 0; kk < 256; kk++) acc += qrow[kk] * S[kk * DVS + j];
            const float* ar = At + i * 32;
#pragma unroll
            for (int m = 0; m < 32; m++) acc += ar[m] * U2[m * DVS + j];
            g_vp[rowbase + ((size_t)i << 10) + dvb + j] = acc;   // delta_out
        }
        __syncthreads();

        // S += k^T @ u2
#pragma unroll 1
        for (int e = tid; e < 256 * DVS; e += 256) {
            int kk = e / DVS, j = e % DVS;
            float acc = S[e];
#pragma unroll
            for (int i = 0; i < 32; i++)
                acc += g_k[rowbase + ((size_t)i << 10) + h * 256 + kk] * U2[i * DVS + j];
            S[e] = acc;
        }
        __syncthreads();
    }
}

// ---------------- FIR convs (K=3 and K=63) over v, tiled ----------------
__global__ __launch_bounds__(256) void fir_kernel(const float* __restrict__ ws,
                                                  const float* __restrict__ wl)
{
    __shared__ float vt[94][64];       // 32+62 rows
    __shared__ float wls[64 * 63];
    __shared__ float wss[64 * 3];
    int cb = blockIdx.x;               // 16
    int lb = blockIdx.y;               // 128 = B * 64
    int b = lb >> 6;
    int l0 = (lb & 63) * 32;
    int c0 = cb * 64;
    int tid = threadIdx.x;

    for (int e = tid; e < 94 * 64; e += 256) {
        int rr = e >> 6, cc = e & 63;
        int l = l0 - 62 + rr;
        vt[rr][cc] = (l >= 0) ? g_v[((size_t)(b * L_ + l) << 10) + c0 + cc] : 0.f;
    }
    for (int e = tid; e < 64 * 63; e += 256) wls[e] = wl[(size_t)c0 * 63 + e];
    for (int e = tid; e < 64 * 3; e += 256)  wss[e] = ws[(size_t)c0 * 3 + e];
    __syncthreads();

    for (int e = tid; e < 32 * 64; e += 256) {
        int i = e >> 6, cc = e & 63;
        float aL = 0.f, aS = 0.f;
        const float* wlr = wls + cc * 63;
#pragma unroll 9
        for (int j = 0; j < 63; j++) aL += vt[i + j][cc] * wlr[j];
        const float* wsr = wss + cc * 3;
#pragma unroll
        for (int j = 0; j < 3; j++) aS += vt[i + 60 + j][cc] * wsr[j];
        size_t gi = ((size_t)(b * L_ + l0 + i) << 10) + c0 + cc;
        g_fl[gi] = aL;
        g_fs[gi] = aS;
    }
}

// ---------------- gate input assembly: [x | stats(fs,fl,delta,v)] ----------------
__global__ void gate_kernel(const float* __restrict__ x)
{
    int r = blockIdx.x, tid = threadIdx.x;
    float* grow = g_gate + (size_t)r * GIN_;
    const float* xr = x + (size_t)r * H_;
    for (int e = tid; e < H_; e += 256) grow[e] = xr[e];

    int wi = tid >> 5, lane = tid & 31;
    for (int p = wi; p < 16; p += 8) {
        int br = p >> 2, h = p & 3;
        const float* src = (br == 0 ? g_fs : br == 1 ? g_fl : br == 2 ? g_vp : g_v)
                           + ((size_t)r << 10) + h * 256;
        float s = 0, s2 = 0;
        for (int d = lane; d < 256; d += 32) { float t = src[d]; s += t; s2 += t * t; }
#pragma unroll
        for (int off = 16; off; off >>= 1) {
            s += __shfl_down_sync(~0u, s, off);
            s2 += __shfl_down_sync(~0u, s2, off);
        }
        if (lane == 0) {
            float mean = s * (1.f / 256.f);
            float var = s2 * (1.f / 256.f) - mean * mean;
            grow[1024 + br * 8 + h] = mean;
            grow[1024 + br * 8 + 4 + h] = sqrtf(fmaxf(var, 1e-6f));
        }
    }
}

// ---------------- MLP second layer: logits = h @ w2 + b2, N=16 ----------------
__global__ void mlp2_kernel(const float* __restrict__ w2, const float* __restrict__ b2)
{
    int r = blockIdx.x, tid = threadIdx.x;  // 128 threads
    float acc[16];
#pragma unroll
    for (int o = 0; o < 16; o++) acc[o] = 0.f;
    const float* hr = g_mlp + (size_t)r * MLPH_;
    for (int kk = tid; kk < MLPH_; kk += 128) {
        float hv = hr[kk];
        const float4* wr = (const float4*)(w2 + (size_t)kk * 16);
        float4 w0 = wr[0], w1 = wr[1], w2v = wr[2], w3 = wr[3];
        acc[0] += hv * w0.x; acc[1] += hv * w0.y; acc[2] += hv * w0.z; acc[3] += hv * w0.w;
        acc[4] += hv * w1.x; acc[5] += hv * w1.y; acc[6] += hv * w1.z; acc[7] += hv * w1.w;
        acc[8] += hv * w2v.x; acc[9] += hv * w2v.y; acc[10] += hv * w2v.z; acc[11] += hv * w2v.w;
        acc[12] += hv * w3.x; acc[13] += hv * w3.y; acc[14] += hv * w3.z; acc[15] += hv * w3.w;
    }
    __shared__ float part[4][16];
    int wi = tid >> 5, lane = tid & 31;
#pragma unroll
    for (int o = 0; o < 16; o++) {
        float v = acc[o];
#pragma unroll
        for (int off = 16; off; off >>= 1) v += __shfl_down_sync(~0u, v, off);
        if (lane == 0) part[wi][o] = v;
    }
    __syncthreads();
    if (tid < 16)
        g_logits[r * 16 + tid] =
            part[0][tid] + part[1][tid] + part[2][tid] + part[3][tid] + b2[tid];
}

// ---------------- softmax gate, combine branches, RMSNorm ----------------
__global__ void combine_kernel(const float* __restrict__ ltemp,
                               const float* __restrict__ onw)
{
    int r = blockIdx.x, tid = threadIdx.x;   // 256 threads, tid = d
    __shared__ float red[256];
    const float* lg = g_logits + r * 16;
#pragma unroll 1
    for (int h = 0; h < 4; h++) {
        float temp = log1pf(expf(ltemp[h])) + 1e-4f;
        float l0 = lg[h * 4 + 0] / temp, l1 = lg[h * 4 + 1] / temp;
        float l2 = lg[h * 4 + 2] / temp, l3 = lg[h * 4 + 3] / temp;
        float mx = fmaxf(fmaxf(l0, l1), fmaxf(l2, l3));
        float e0 = expf(l0 - mx), e1 = expf(l1 - mx), e2 = expf(l2 - mx), e3 = expf(l3 - mx);
        float inv = 1.f / (e0 + e1 + e2 + e3);
        size_t idx = ((size_t)r << 10) + h * 256 + tid;
        float ov = (e0 * g_fs[idx] + e1 * g_fl[idx] + e2 * g_vp[idx] + e3 * g_v[idx]) * inv;
        red[tid] = ov * ov;
        __syncthreads();
        for (int s = 128; s; s >>= 1) { if (tid < s) red[tid] += red[tid + s]; __syncthreads(); }
        float scale = rsqrtf(red[0] * (1.f / 256.f) + 1e-5f);
        g_oc[idx] = ov * scale * onw[tid];
        __syncthreads();
    }
}

// ---------------- launch ----------------
extern "C" void kernel_launch(void* const* d_in, const int* in_sizes, int n_in,
                              void* d_out, int out_size)
{
    const float* x   = (const float*)d_in[0];
    const float* Wq  = (const float*)d_in[1];
    const float* Wk  = (const float*)d_in[2];
    const float* Wv  = (const float*)d_in[3];
    const float* Wb  = (const float*)d_in[4];
    const float* cq  = (const float*)d_in[5];
    const float* ck  = (const float*)d_in[6];
    const float* cv  = (const float*)d_in[7];
    const float* fsw = (const float*)d_in[8];
    const float* flw = (const float*)d_in[9];
    const float* w1  = (const float*)d_in[10];
    const float* b1  = (const float*)d_in[11];
    const float* w2  = (const float*)d_in[12];
    const float* b2  = (const float*)d_in[13];
    const float* lt  = (const float*)d_in[14];
    const float* onw = (const float*)d_in[15];
    const float* Wo  = (const float*)d_in[16];
    float* out = (float*)d_out;

    void* p;
    float *qp, *kp, *vp, *qq, *kk_, *vv, *gate, *mlp, *oc;
    __nv_bfloat16 *wqh, *wql, *wkh, *wkl, *wvh, *wvl, *w1h, *w1l, *woh, *wol;
    cudaGetSymbolAddress(&p, g_qp);  qp = (float*)p;
    cudaGetSymbolAddress(&p, g_kp);  kp = (float*)p;
    cudaGetSymbolAddress(&p, g_vp);  vp = (float*)p;
    cudaGetSymbolAddress(&p, g_q);   qq = (float*)p;
    cudaGetSymbolAddress(&p, g_k);   kk_ = (float*)p;
    cudaGetSymbolAddress(&p, g_v);   vv = (float*)p;
    cudaGetSymbolAddress(&p, g_gate); gate = (float*)p;
    cudaGetSymbolAddress(&p, g_mlp); mlp = (float*)p;
    cudaGetSymbolAddress(&p, g_oc);  oc = (float*)p;
    cudaGetSymbolAddress(&p, g_wqh); wqh = (__nv_bfloat16*)p;
    cudaGetSymbolAddress(&p, g_wql); wql = (__nv_bfloat16*)p;
    cudaGetSymbolAddress(&p, g_wkh); wkh = (__nv_bfloat16*)p;
    cudaGetSymbolAddress(&p, g_wkl); wkl = (__nv_bfloat16*)p;
    cudaGetSymbolAddress(&p, g_wvh); wvh = (__nv_bfloat16*)p;
    cudaGetSymbolAddress(&p, g_wvl); wvl = (__nv_bfloat16*)p;
    cudaGetSymbolAddress(&p, g_w1h); w1h = (__nv_bfloat16*)p;
    cudaGetSymbolAddress(&p, g_w1l); w1l = (__nv_bfloat16*)p;
    cudaGetSymbolAddress(&p, g_woh); woh = (__nv_bfloat16*)p;
    cudaGetSymbolAddress(&p, g_wol); wol = (__nv_bfloat16*)p;

    dim3 thr(256);
    dim3 wb(32, 8);
    // 0. weight split/transpose (per-launch; cheap)
    wconv_kernel<<<dim3(32, 32), wb>>>(Wq, wqh, wql, H_, H_);
    wconv_kernel<<<dim3(32, 32), wb>>>(Wk, wkh, wkl, H_, H_);
    wconv_kernel<<<dim3(32, 32), wb>>>(Wv, wvh, wvl, H_, H_);
    wconv_kernel<<<dim3(MLPH_ / 32, GIN_ / 32), wb>>>(w1, w1h, w1l, GIN_, MLPH_);
    wconv_kernel<<<dim3(32, 32), wb>>>(Wo, woh, wol, H_, H_);
    // 1. projections (tensor core)
    gemm_tc<<<dim3(H_ / 128, R_ / 128), thr>>>(x, wqh, wql, nullptr, qp, R_, H_, H_, 0);
    gemm_tc<<<dim3(H_ / 128, R_ / 128), thr>>>(x, wkh, wkl, nullptr, kp, R_, H_, H_, 0);
    gemm_tc<<<dim3(H_ / 128, R_ / 128), thr>>>(x, wvh, wvl, nullptr, vp, R_, H_, H_, 0);
    beta_kernel<<<R_ / 4, 128>>>(x, Wb);
    // 2. short convs + silu
    conv_silu_kernel<<<R_ * H_ / 256, thr>>>(qp, cq, qq);
    conv_silu_kernel<<<R_ * H_ / 256, thr>>>(kp, ck, kk_);
    conv_silu_kernel<<<R_ * H_ / 256, thr>>>(vp, cv, vv);
    // 3. delta precompute (u -> g_qp, w -> g_kp; qn/kn in place)
    size_t smemP = (size_t)(4 * 32 * RS + 2048) * sizeof(float);
    cudaFuncSetAttribute(precomp_kernel, cudaFuncAttributeMaxDynamicSharedMemorySize, (int)smemP);
    precomp_kernel<<<B_ * NH_ * NCH_, thr, smemP>>>();
    // 4. sequential scan (delta_out -> g_vp)
    scan_kernel<<<B_ * NH_ * (DV_ / DVS), thr>>>();
    // 5. FIR convs
    fir_kernel<<<dim3(H_ / 64, B_ * L_ / 32), thr>>>(fsw, flw);
    // 6. gate input
    gate_kernel<<<R_, thr>>>(x);
    // 7. MLP (tensor core first layer, gelu fused)
    gemm_tc<<<dim3(MLPH_ / 128, R_ / 128), thr>>>(gate, w1h, w1l, b1, mlp, R_, MLPH_, GIN_, 1);
    mlp2_kernel<<<R_, 128>>>(w2, b2);
    // 8. combine + RMSNorm
    combine_kernel<<<R_, thr>>>(lt, onw);
    // 9. output projection (tensor core)
    gemm_tc<<<dim3(H_ / 128, R_ / 128), thr>>>(oc, woh, wol, nullptr, out, R_, H_, H_, 0);
}

// round 4
// speedup vs baseline: 2.8604x; 2.4954x over previous
#include <cuda_runtime.h>
#include <cuda_bf16.h>
#include <stdint.h>
#include <math.h>

#define B_   2
#define L_   2048
#define H_   1024
#define NH_  4
#define R_   (B_ * L_)       // 4096 rows
#define NCH_ 64              // chunks of 32 per sequence
#define GIN_ 1056
#define MLPH_ 2048
#define DVS  16

// ---------------- scratch ----------------
__device__ __align__(128) float g_qkv[(size_t)R_ * 3 * H_]; // packed qkv projection
__device__ __align__(128) float g_qp[R_ * H_];     // u
__device__ __align__(128) float g_kp[R_ * H_];     // w
__device__ __align__(128) float g_vp[R_ * H_];     // delta_out
__device__ __align__(128) float g_q[R_ * H_];
__device__ __align__(128) float g_k[R_ * H_];
__device__ __align__(128) float g_v[R_ * H_];
__device__ __align__(128) float g_beta[R_ * NH_];
__device__ __align__(128) float g_attn[(size_t)B_ * NH_ * NCH_ * 32 * 32];
__device__ __align__(128) float g_fs[R_ * H_];
__device__ __align__(128) float g_fl[R_ * H_];
__device__ __align__(128) float g_gate[(size_t)R_ * GIN_];
__device__ __align__(128) float g_mlp[(size_t)R_ * MLPH_];
__device__ __align__(128) float g_logits[R_ * 16];
__device__ __align__(128) float g_oc[R_ * H_];

// bf16 split weights [N][K] (QKV packed: 3072 x 1024)
__device__ __align__(128) __nv_bfloat16 g_wh[3 * H_ * H_], g_wl[3 * H_ * H_];
__device__ __align__(128) __nv_bfloat16 g_w1h[MLPH_ * GIN_], g_w1l[MLPH_ * GIN_];
__device__ __align__(128) __nv_bfloat16 g_woh[H_ * H_], g_wol[H_ * H_];
// bf16 split activations
__device__ __align__(128) __nv_bfloat16 g_xh[R_ * H_], g_xl[R_ * H_];     // x, later reused for oc
__device__ __align__(128) __nv_bfloat16 g_gh[(size_t)R_ * GIN_], g_gl[(size_t)R_ * GIN_];

// ---------------- cp.async helpers ----------------
__device__ __forceinline__ void cpa16(uint32_t dst, const void* src) {
    asm volatile("cp.async.cg.shared.global [%0], [%1], 16;" :: "r"(dst), "l"(src));
}
#define CPA_COMMIT asm volatile("cp.async.commit_group;")

// ---------------- elementwise fp32 -> bf16 hi/lo split ----------------
__global__ void split_kernel(const float* __restrict__ A,
                             __nv_bfloat16* __restrict__ Ah,
                             __nv_bfloat16* __restrict__ Al, int n)
{
    int i = blockIdx.x * 256 + threadIdx.x;
    if (i < n) {
        float v = A[i];
        __nv_bfloat16 h = __float2bfloat16(v);
        Ah[i] = h;
        Al[i] = __float2bfloat16(v - __bfloat162float(h));
    }
}

// ---------------- weight transpose + split: W [K][N] -> [N][K] bf16 ----------------
__global__ void wconv_kernel(const float* __restrict__ W,
                             __nv_bfloat16* __restrict__ Th,
                             __nv_bfloat16* __restrict__ Tl, int K, int N)
{
    __shared__ float t[32][33];
    int k0 = blockIdx.y * 32, n0 = blockIdx.x * 32;
    int tx = threadIdx.x, ty = threadIdx.y;
    for (int i = ty; i < 32; i += 8)
        t[i][tx] = W[(size_t)(k0 + i) * N + n0 + tx];
    __syncthreads();
    for (int i = ty; i < 32; i += 8) {
        float v = t[tx][i];
        __nv_bfloat16 hi = __float2bfloat16(v);
        __nv_bfloat16 lo = __float2bfloat16(v - __bfloat162float(hi));
        size_t o = (size_t)(n0 + i) * K + k0 + tx;
        Th[o] = hi; Tl[o] = lo;
    }
}

// QKV 3-in-1 packed variant (K=N=1024 each, packed rows at z*H)
__global__ void wconv3_kernel(const float* __restrict__ Wq,
                              const float* __restrict__ Wk,
                              const float* __restrict__ Wv)
{
    __shared__ float t[32][33];
    int z = blockIdx.z;
    const float* W = (z == 0) ? Wq : (z == 1) ? Wk : Wv;
    int k0 = blockIdx.y * 32, n0 = blockIdx.x * 32;
    int tx = threadIdx.x, ty = threadIdx.y;
    for (int i = ty; i < 32; i += 8)
        t[i][tx] = W[(size_t)(k0 + i) * H_ + n0 + tx];
    __syncthreads();
    size_t base = (size_t)z * H_ * H_;
    for (int i = ty; i < 32; i += 8) {
        float v = t[tx][i];
        __nv_bfloat16 hi = __float2bfloat16(v);
        __nv_bfloat16 lo = __float2bfloat16(v - __bfloat162float(hi));
        size_t o = base + (size_t)(n0 + i) * H_ + k0 + tx;
        g_wh[o] = hi; g_wl[o] = lo;
    }
}

// ---------------- tensor-core GEMM, pre-split bf16 A and B ----------------
// C[M,N] = act(Ah@Bh + Al@Bh + Ah@Bl + bias); A [M][K] bf16 pair, B [N][K] bf16 pair.
// BM=BN=128, BK=32, 256 threads, cp.async double-buffered.
#define MMA16816(d, a, b0, b1) \
  asm volatile("mma.sync.aligned.m16n8k16.row.col.f32.bf16.bf16.f32 " \
    "{%0,%1,%2,%3}, {%4,%5,%6,%7}, {%8,%9}, {%0,%1,%2,%3};" \
    : "+f"(d[0]), "+f"(d[1]), "+f"(d[2]), "+f"(d[3]) \
    : "r"(a[0]), "r"(a[1]), "r"(a[2]), "r"(a[3]), "r"(b0), "r"(b1))

#define ASTR 40   // halves per row (32 + 8 pad)
#define STAGE_HALVES (4 * 128 * ASTR)

__global__ __launch_bounds__(256) void gemm_bf(
    const __nv_bfloat16* __restrict__ Ahg, const __nv_bfloat16* __restrict__ Alg,
    const __nv_bfloat16* __restrict__ Bhg, const __nv_bfloat16* __restrict__ Blg,
    const float* __restrict__ bias, float* __restrict__ C,
    int M, int N, int K, int act)
{
    extern __shared__ __nv_bfloat16 smh[];
    int tid = threadIdx.x;
    int row0 = blockIdx.y * 128, col0 = blockIdx.x * 128;
    int wid = tid >> 5, lane = tid & 31;
    int wm = (wid >> 1) * 32, wn = (wid & 1) * 64;
    int g = lane >> 2, t = lane & 3;

    float acc[2][8][4];
#pragma unroll
    for (int i = 0; i < 2; i++)
#pragma unroll
        for (int j = 0; j < 8; j++)
#pragma unroll
            for (int q = 0; q < 4; q++) acc[i][j][q] = 0.f;

    const __nv_bfloat16* gsrc[4] = {Ahg, Alg, Bhg, Blg};
    int gr0[4] = {row0, row0, col0, col0};

    // loader: per array 512 16B-segments (128 rows x 4 segs), 2 per thread
    auto load_stage = [&](int s, int k0) {
        __nv_bfloat16* sp = smh + s * STAGE_HALVES;
#pragma unroll
        for (int a = 0; a < 4; a++) {
#pragma unroll
            for (int q = 0; q < 2; q++) {
                int c = tid * 2 + q;          // 0..511
                int r = c >> 2, seg = c & 3;
                uint32_t d = (uint32_t)__cvta_generic_to_shared(
                    sp + a * 128 * ASTR + r * ASTR + seg * 8);
                cpa16(d, gsrc[a] + (size_t)(gr0[a] + r) * K + k0 + seg * 8);
            }
        }
        CPA_COMMIT;
    };

    load_stage(0, 0);
    int nk = K / 32;
    for (int ki = 0; ki < nk; ki++) {
        if (ki + 1 < nk) {
            load_stage((ki + 1) & 1, (ki + 1) * 32);
            asm volatile("cp.async.wait_group 1;");
        } else {
            asm volatile("cp.async.wait_group 0;");
        }
        __syncthreads();
        __nv_bfloat16* sp = smh + (ki & 1) * STAGE_HALVES;
        __nv_bfloat16* Ah = sp;
        __nv_bfloat16* Al = sp + 128 * ASTR;
        __nv_bfloat16* Bh = sp + 2 * 128 * ASTR;
        __nv_bfloat16* Bl = sp + 3 * 128 * ASTR;
#pragma unroll
        for (int ks = 0; ks < 2; ks++) {
            int ko = ks * 16;
            uint32_t afh[2][4], afl[2][4];
#pragma unroll
            for (int mi = 0; mi < 2; mi++) {
                int mb = wm + mi * 16;
                afh[mi][0] = *(const uint32_t*)&Ah[(mb + g)     * ASTR + ko + 2 * t];
                afh[mi][1] = *(const uint32_t*)&Ah[(mb + 8 + g) * ASTR + ko + 2 * t];
                afh[mi][2] = *(const uint32_t*)&Ah[(mb + g)     * ASTR + ko + 2 * t + 8];
                afh[mi][3] = *(const uint32_t*)&Ah[(mb + 8 + g) * ASTR + ko + 2 * t + 8];
                afl[mi][0] = *(const uint32_t*)&Al[(mb + g)     * ASTR + ko + 2 * t];
                afl[mi][1] = *(const uint32_t*)&Al[(mb + 8 + g) * ASTR + ko + 2 * t];
                afl[mi][2] = *(const uint32_t*)&Al[(mb + g)     * ASTR + ko + 2 * t + 8];
                afl[mi][3] = *(const uint32_t*)&Al[(mb + 8 + g) * ASTR + ko + 2 * t + 8];
            }
#pragma unroll
            for (int ni = 0; ni < 8; ni++) {
                int nb = wn + ni * 8;
                uint32_t bh0 = *(const uint32_t*)&Bh[(nb + g) * ASTR + ko + 2 * t];
                uint32_t bh1 = *(const uint32_t*)&Bh[(nb + g) * ASTR + ko + 2 * t + 8];
                uint32_t bl0 = *(const uint32_t*)&Bl[(nb + g) * ASTR + ko + 2 * t];
                uint32_t bl1 = *(const uint32_t*)&Bl[(nb + g) * ASTR + ko + 2 * t + 8];
#pragma unroll
                for (int mi = 0; mi < 2; mi++) {
                    MMA16816(acc[mi][ni], afh[mi], bh0, bh1);
                    MMA16816(acc[mi][ni], afl[mi], bh0, bh1);
                    MMA16816(acc[mi][ni], afh[mi], bl0, bl1);
                }
            }
        }
        __syncthreads();
    }

#pragma unroll
    for (int mi = 0; mi < 2; mi++)
#pragma unroll
        for (int ni = 0; ni < 8; ni++) {
            int r = row0 + wm + mi * 16 + g;
            int c = col0 + wn + ni * 8 + 2 * t;
            float v[4];
#pragma unroll
            for (int q = 0; q < 4; q++) {
                float x = acc[mi][ni][q];
                if (bias) x += bias[c + (q & 1)];
                if (act == 1) x = 0.5f * x * (1.f + erff(x * 0.70710678118654752f));
                v[q] = x;
            }
            *(float2*)(C + (size_t)r * N + c)       = make_float2(v[0], v[1]);
            *(float2*)(C + (size_t)(r + 8) * N + c) = make_float2(v[2], v[3]);
        }
}

// ---------------- beta ----------------
__global__ void beta_kernel(const float* __restrict__ x, const float* __restrict__ Wb)
{
    int r = blockIdx.x * 4 + (threadIdx.x >> 5);
    int lane = threadIdx.x & 31;
    float acc0 = 0, acc1 = 0, acc2 = 0, acc3 = 0;
    const float* xr = x + (size_t)r * H_;
    for (int kk = lane; kk < H_; kk += 32) {
        float xv = xr[kk];
        const float* w = Wb + kk * 4;
        acc0 += xv * w[0]; acc1 += xv * w[1]; acc2 += xv * w[2]; acc3 += xv * w[3];
    }
#pragma unroll
    for (int off = 16; off; off >>= 1) {
        acc0 += __shfl_down_sync(~0u, acc0, off);
        acc1 += __shfl_down_sync(~0u, acc1, off);
        acc2 += __shfl_down_sync(~0u, acc2, off);
        acc3 += __shfl_down_sync(~0u, acc3, off);
    }
    if (lane == 0) {
        g_beta[r * 4 + 0] = 1.f / (1.f + expf(-acc0));
        g_beta[r * 4 + 1] = 1.f / (1.f + expf(-acc1));
        g_beta[r * 4 + 2] = 1.f / (1.f + expf(-acc2));
        g_beta[r * 4 + 3] = 1.f / (1.f + expf(-acc3));
    }
}

// ---------------- causal conv K=4 + silu (reads packed qkv) ----------------
__global__ void conv_silu_kernel(const float* __restrict__ src,
                                 const float* __restrict__ w,
                                 float* __restrict__ dst, int srcStride, int srcOff)
{
    int tid = blockIdx.x * blockDim.x + threadIdx.x;
    int c = tid & (H_ - 1);
    int r = tid >> 10;
    int b = r >> 11;
    int l = r & (L_ - 1);
    const float* wc = w + c * 4;
    float acc = 0.f;
#pragma unroll
    for (int j = 0; j < 4; j++) {
        int ll = l - 3 + j;
        if (ll >= 0) acc += src[(size_t)(b * L_ + ll) * srcStride + srcOff + c] * wc[j];
    }
    dst[tid] = acc / (1.f + expf(-acc));
}

// ---------------- delta precompute ----------------
#define RS 257
__global__ __launch_bounds__(256) void precomp_kernel()
{
    extern __shared__ float sm[];
    float* Qs = sm;
    float* Ks = Qs + 32 * RS;
    float* KB = Ks + 32 * RS;
    float* VB = KB + 32 * RS;
    float* Am = VB + 32 * RS;
    float* Tm = Am + 1024;
    __shared__ float rbeta[32], qn_s[32], kn_s[32];

    int bhn = blockIdx.x;
    int n = bhn % NCH_; int bh = bhn / NCH_;
    int b = bh >> 2, h = bh & 3;
    int l0 = n * 32;
    int tid = threadIdx.x, wi = tid >> 5, lane = tid & 31;

    for (int e = tid; e < 8192; e += 256) {
        int i = e >> 8, d = e & 255;
        size_t gi = ((size_t)(b * L_ + l0 + i) << 10) + h * 256 + d;
        Qs[i * RS + d] = g_q[gi];
        Ks[i * RS + d] = g_k[gi];
    }
    if (tid < 32) rbeta[tid] = g_beta[(b * L_ + l0 + tid) * 4 + h];
    __syncthreads();

    for (int rr = wi; rr < 32; rr += 8) {
        float sq = 0, sk = 0;
        for (int d = lane; d < 256; d += 32) {
            float a = Qs[rr * RS + d]; sq += a * a;
            float c = Ks[rr * RS + d]; sk += c * c;
        }
#pragma unroll
        for (int off = 16; off; off >>= 1) {
            sq += __shfl_down_sync(~0u, sq, off);
            sk += __shfl_down_sync(~0u, sk, off);
        }
        if (lane == 0) { qn_s[rr] = rsqrtf(sq + 1e-6f); kn_s[rr] = rsqrtf(sk + 1e-6f); }
    }
    __syncthreads();

    for (int e = tid; e < 8192; e += 256) {
        int i = e >> 8, d = e & 255;
        size_t gi = ((size_t)(b * L_ + l0 + i) << 10) + h * 256 + d;
        float qv = Qs[i * RS + d] * qn_s[i]; Qs[i * RS + d] = qv;
        float kv = Ks[i * RS + d] * kn_s[i]; Ks[i * RS + d] = kv;
        KB[i * RS + d] = kv * rbeta[i];
        VB[i * RS + d] = g_v[gi] * rbeta[i];
        g_q[gi] = qv; g_k[gi] = kv;
    }
    __syncthreads();

    for (int e = tid; e < 1024; e += 256) {
        int i = e >> 5, j = e & 31;
        float s = 0.f;
        if (j < i) {
            const float* a = KB + i * RS; const float* c = Ks + j * RS;
            for (int d = 0; d < 256; d++) s += a[d] * c[d];
        }
        Am[e] = s;
    }
    __syncthreads();

    if (wi == 0) {
        int j = lane;
        for (int i = 0; i < 32; i++) {
            float val = (i == j) ? 1.f : 0.f;
            for (int m = j; m < i; m++) val -= Am[i * 32 + m] * Tm[m * 32 + j];
            Tm[i * 32 + j] = val;
            __syncwarp();
        }
    }
    __syncthreads();

    float* attn_out = g_attn + (((size_t)bh * NCH_ + n) << 10);
    for (int e = tid; e < 1024; e += 256) {
        int i = e >> 5, j = e & 31;
        float s = 0.f;
        if (j <= i) {
            const float* a = Qs + i * RS; const float* c = Ks + j * RS;
            for (int d = 0; d < 256; d++) s += a[d] * c[d];
        }
        attn_out[e] = s;
    }

    for (int e = tid; e < 8192; e += 256) {
        int i = e >> 8, d = e & 255;
        float su = 0, sw = 0;
        const float* tr = Tm + i * 32;
#pragma unroll
        for (int m = 0; m < 32; m++) {
            float t = tr[m];
            su += t * VB[m * RS + d];
            sw += t * KB[m * RS + d];
        }
        size_t gi = ((size_t)(b * L_ + l0 + i) << 10) + h * 256 + d;
        g_qp[gi] = su;
        g_kp[gi] = sw;
    }
}

// ---------------- sequential scan: smem-staged + cp.async double buffer ----------------
// grid = 128 blocks (8 bh x 16 slices), 512 threads, ~222 KB dynamic smem.
__global__ __launch_bounds__(512) void scan_kernel()
{
    extern __shared__ float sm[];
    float* S  = sm;             // 256*16
    float* Wt = sm + 4096;      // 2 x 32*256
    float* Qt = Wt + 16384;
    float* Kt = Qt + 16384;
    float* Ut = Kt + 16384;     // 2 x 32*16
    float* At = Ut + 1024;      // 2 x 32*32
    float* U2 = At + 2048;      // 32*16

    int blk = blockIdx.x;
    int bh = blk >> 4, slice = blk & 15;
    int b = bh >> 2, h = bh & 3;
    int tid = threadIdx.x;
    int dvb = h * 256 + slice * DVS;

    for (int e = tid; e < 4096; e += 512) S[e] = 0.f;

    auto issue = [&](int n, int buf) {
        size_t rowbase = ((size_t)(b * L_ + n * 32)) << 10;
        const float* srcs[3] = {g_kp + rowbase + h * 256,
                                g_q  + rowbase + h * 256,
                                g_k  + rowbase + h * 256};
        float* dsts[3] = {Wt + buf * 8192, Qt + buf * 8192, Kt + buf * 8192};
#pragma unroll
        for (int a = 0; a < 3; a++) {
#pragma unroll
            for (int s = 0; s < 4; s++) {
                int c = tid + s * 512;             // 0..2047
                int row = c >> 6, seg = c & 63;    // 64 x 16B per row
                uint32_t d = (uint32_t)__cvta_generic_to_shared(dsts[a] + row * 256 + seg * 4);
                cpa16(d, srcs[a] + ((size_t)row << 10) + seg * 4);
            }
        }
        if (tid < 128) {   // u slice: 32 rows x 16 floats
            int row = tid >> 2, seg = tid & 3;
            uint32_t d = (uint32_t)__cvta_generic_to_shared(Ut + buf * 512 + row * 16 + seg * 4);
            cpa16(d, g_qp + rowbase + ((size_t)row << 10) + dvb + seg * 4);
        }
        if (tid < 256) {   // attn: 1024 floats
            const float* attn_n = g_attn + (((size_t)bh * NCH_ + n) << 10);
            uint32_t d = (uint32_t)__cvta_generic_to_shared(At + buf * 1024 + tid * 4);
            cpa16(d, attn_n + tid * 4);
        }
        CPA_COMMIT;
    };

    issue(0, 0);

#pragma unroll 1
    for (int n = 0; n < NCH_; n++) {
        int cur = n & 1;
        if (n + 1 < NCH_) {
            issue(n + 1, cur ^ 1);
            asm volatile("cp.async.wait_group 1;");
        } else {
            asm volatile("cp.async.wait_group 0;");
        }
        __syncthreads();

        // u2 = u - w @ S   (512 elems, 1/thread)
        {
            int i = tid >> 4, j = tid & 15;
            const float* wr = Wt + cur * 8192 + i * 256;
            float acc = Ut[cur * 512 + i * 16 + j];
#pragma unroll 8
            for (int kk = 0; kk < 256; kk++) acc -= wr[kk] * S[kk * 16 + j];
            U2[i * 16 + j] = acc;
        }
        __syncthreads();

        // o = q @ S + attn @ u2
        {
            int i = tid >> 4, j = tid & 15;
            const float* qr = Qt + cur * 8192 + i * 256;
            float acc = 0.f;
#pragma unroll 8
            for (int kk = 0; kk < 256; kk++) acc += qr[kk] * S[kk * 16 + j];
            const float* ar = At + cur * 1024 + i * 32;
#pragma unroll
            for (int m = 0; m < 32; m++) acc += ar[m] * U2[m * 16 + j];
            size_t rowbase = ((size_t)(b * L_ + n * 32)) << 10;
            g_vp[rowbase + ((size_t)i << 10) + dvb + j] = acc;
        }
        __syncthreads();

        // S += k^T @ u2   (4096 elems, 8/thread)
#pragma unroll
        for (int p = 0; p < 8; p++) {
            int e = tid + p * 512;
            int kk = e >> 4, j = e & 15;
            float acc = S[e];
            const float* kb = Kt + cur * 8192;
#pragma unroll
            for (int i = 0; i < 32; i++)
                acc += kb[i * 256 + kk] * U2[i * 16 + j];
            S[e] = acc;
        }
        __syncthreads();
    }
}

// ---------------- FIR convs ----------------
__global__ __launch_bounds__(256) void fir_kernel(const float* __restrict__ ws,
                                                  const float* __restrict__ wl)
{
    __shared__ float vt[94][64];
    __shared__ float wls[64 * 63];
    __shared__ float wss[64 * 3];
    int cb = blockIdx.x;
    int lb = blockIdx.y;
    int b = lb >> 6;
    int l0 = (lb & 63) * 32;
    int c0 = cb * 64;
    int tid = threadIdx.x;

    for (int e = tid; e < 94 * 64; e += 256) {
        int rr = e >> 6, cc = e & 63;
        int l = l0 - 62 + rr;
        vt[rr][cc] = (l >= 0) ? g_v[((size_t)(b * L_ + l) << 10) + c0 + cc] : 0.f;
    }
    for (int e = tid; e < 64 * 63; e += 256) wls[e] = wl[(size_t)c0 * 63 + e];
    for (int e = tid; e < 64 * 3; e += 256)  wss[e] = ws[(size_t)c0 * 3 + e];
    __syncthreads();

    for (int e = tid; e < 32 * 64; e += 256) {
        int i = e >> 6, cc = e & 63;
        float aL = 0.f, aS = 0.f;
        const float* wlr = wls + cc * 63;
#pragma unroll 9
        for (int j = 0; j < 63; j++) aL += vt[i + j][cc] * wlr[j];
        const float* wsr = wss + cc * 3;
#pragma unroll
        for (int j = 0; j < 3; j++) aS += vt[i + 60 + j][cc] * wsr[j];
        size_t gi = ((size_t)(b * L_ + l0 + i) << 10) + c0 + cc;
        g_fl[gi] = aL;
        g_fs[gi] = aS;
    }
}

// ---------------- gate input ----------------
__global__ void gate_kernel(const float* __restrict__ x)
{
    int r = blockIdx.x, tid = threadIdx.x;
    float* grow = g_gate + (size_t)r * GIN_;
    const float* xr = x + (size_t)r * H_;
    for (int e = tid; e < H_; e += 256) grow[e] = xr[e];

    int wi = tid >> 5, lane = tid & 31;
    for (int p = wi; p < 16; p += 8) {
        int br = p >> 2, h = p & 3;
        const float* src = (br == 0 ? g_fs : br == 1 ? g_fl : br == 2 ? g_vp : g_v)
                           + ((size_t)r << 10) + h * 256;
        float s = 0, s2 = 0;
        for (int d = lane; d < 256; d += 32) { float t = src[d]; s += t; s2 += t * t; }
#pragma unroll
        for (int off = 16; off; off >>= 1) {
            s += __shfl_down_sync(~0u, s, off);
            s2 += __shfl_down_sync(~0u, s2, off);
        }
        if (lane == 0) {
            float mean = s * (1.f / 256.f);
            float var = s2 * (1.f / 256.f) - mean * mean;
            grow[1024 + br * 8 + h] = mean;
            grow[1024 + br * 8 + 4 + h] = sqrtf(fmaxf(var, 1e-6f));
        }
    }
}

// ---------------- MLP2 ----------------
__global__ void mlp2_kernel(const float* __restrict__ w2, const float* __restrict__ b2)
{
    int r = blockIdx.x, tid = threadIdx.x;
    float acc[16];
#pragma unroll
    for (int o = 0; o < 16; o++) acc[o] = 0.f;
    const float* hr = g_mlp + (size_t)r * MLPH_;
    for (int kk = tid; kk < MLPH_; kk += 128) {
        float hv = hr[kk];
        const float4* wr = (const float4*)(w2 + (size_t)kk * 16);
        float4 w0 = wr[0], w1 = wr[1], w2v = wr[2], w3 = wr[3];
        acc[0] += hv * w0.x; acc[1] += hv * w0.y; acc[2] += hv * w0.z; acc[3] += hv * w0.w;
        acc[4] += hv * w1.x; acc[5] += hv * w1.y; acc[6] += hv * w1.z; acc[7] += hv * w1.w;
        acc[8] += hv * w2v.x; acc[9] += hv * w2v.y; acc[10] += hv * w2v.z; acc[11] += hv * w2v.w;
        acc[12] += hv * w3.x; acc[13] += hv * w3.y; acc[14] += hv * w3.z; acc[15] += hv * w3.w;
    }
    __shared__ float part[4][16];
    int wi = tid >> 5, lane = tid & 31;
#pragma unroll
    for (int o = 0; o < 16; o++) {
        float v = acc[o];
#pragma unroll
        for (int off = 16; off; off >>= 1) v += __shfl_down_sync(~0u, v, off);
        if (lane == 0) part[wi][o] = v;
    }
    __syncthreads();
    if (tid < 16)
        g_logits[r * 16 + tid] =
            part[0][tid] + part[1][tid] + part[2][tid] + part[3][tid] + b2[tid];
}

// ---------------- combine + RMSNorm ----------------
__global__ void combine_kernel(const float* __restrict__ ltemp,
                               const float* __restrict__ onw)
{
    int r = blockIdx.x, tid = threadIdx.x;
    __shared__ float red[256];
    const float* lg = g_logits + r * 16;
#pragma unroll 1
    for (int h = 0; h < 4; h++) {
        float temp = log1pf(expf(ltemp[h])) + 1e-4f;
        float l0 = lg[h * 4 + 0] / temp, l1 = lg[h * 4 + 1] / temp;
        float l2 = lg[h * 4 + 2] / temp, l3 = lg[h * 4 + 3] / temp;
        float mx = fmaxf(fmaxf(l0, l1), fmaxf(l2, l3));
        float e0 = expf(l0 - mx), e1 = expf(l1 - mx), e2 = expf(l2 - mx), e3 = expf(l3 - mx);
        float inv = 1.f / (e0 + e1 + e2 + e3);
        size_t idx = ((size_t)r << 10) + h * 256 + tid;
        float ov = (e0 * g_fs[idx] + e1 * g_fl[idx] + e2 * g_vp[idx] + e3 * g_v[idx]) * inv;
        red[tid] = ov * ov;
        __syncthreads();
        for (int s = 128; s; s >>= 1) { if (tid < s) red[tid] += red[tid + s]; __syncthreads(); }
        float scale = rsqrtf(red[0] * (1.f / 256.f) + 1e-5f);
        g_oc[idx] = ov * scale * onw[tid];
        __syncthreads();
    }
}

// ---------------- launch ----------------
extern "C" void kernel_launch(void* const* d_in, const int* in_sizes, int n_in,
                              void* d_out, int out_size)
{
    const float* x   = (const float*)d_in[0];
    const float* Wq  = (const float*)d_in[1];
    const float* Wk  = (const float*)d_in[2];
    const float* Wv  = (const float*)d_in[3];
    const float* Wb  = (const float*)d_in[4];
    const float* cq  = (const float*)d_in[5];
    const float* ck  = (const float*)d_in[6];
    const float* cv  = (const float*)d_in[7];
    const float* fsw = (const float*)d_in[8];
    const float* flw = (const float*)d_in[9];
    const float* w1  = (const float*)d_in[10];
    const float* b1  = (const float*)d_in[11];
    const float* w2  = (const float*)d_in[12];
    const float* b2  = (const float*)d_in[13];
    const float* lt  = (const float*)d_in[14];
    const float* onw = (const float*)d_in[15];
    const float* Wo  = (const float*)d_in[16];
    float* out = (float*)d_out;

    void* p;
    float *qkv, *qq, *kk_, *vv, *gate, *mlp, *oc;
    __nv_bfloat16 *wh, *wl, *w1h, *w1l, *woh, *wol, *xh, *xl, *gh, *gl;
    cudaGetSymbolAddress(&p, g_qkv); qkv = (float*)p;
    cudaGetSymbolAddress(&p, g_q);   qq = (float*)p;
    cudaGetSymbolAddress(&p, g_k);   kk_ = (float*)p;
    cudaGetSymbolAddress(&p, g_v);   vv = (float*)p;
    cudaGetSymbolAddress(&p, g_gate); gate = (float*)p;
    cudaGetSymbolAddress(&p, g_mlp); mlp = (float*)p;
    cudaGetSymbolAddress(&p, g_oc);  oc = (float*)p;
    cudaGetSymbolAddress(&p, g_wh);  wh = (__nv_bfloat16*)p;
    cudaGetSymbolAddress(&p, g_wl);  wl = (__nv_bfloat16*)p;
    cudaGetSymbolAddress(&p, g_w1h); w1h = (__nv_bfloat16*)p;
    cudaGetSymbolAddress(&p, g_w1l); w1l = (__nv_bfloat16*)p;
    cudaGetSymbolAddress(&p, g_woh); woh = (__nv_bfloat16*)p;
    cudaGetSymbolAddress(&p, g_wol); wol = (__nv_bfloat16*)p;
    cudaGetSymbolAddress(&p, g_xh);  xh = (__nv_bfloat16*)p;
    cudaGetSymbolAddress(&p, g_xl);  xl = (__nv_bfloat16*)p;
    cudaGetSymbolAddress(&p, g_gh);  gh = (__nv_bfloat16*)p;
    cudaGetSymbolAddress(&p, g_gl);  gl = (__nv_bfloat16*)p;

    static int attr_done = 0;
    if (!attr_done) {
        cudaFuncSetAttribute(gemm_bf, cudaFuncAttributeMaxDynamicSharedMemorySize,
                             2 * STAGE_HALVES * (int)sizeof(__nv_bfloat16));
        cudaFuncSetAttribute(precomp_kernel, cudaFuncAttributeMaxDynamicSharedMemorySize,
                             (4 * 32 * RS + 2048) * (int)sizeof(float));
        cudaFuncSetAttribute(scan_kernel, cudaFuncAttributeMaxDynamicSharedMemorySize,
                             56832 * (int)sizeof(float));
        attr_done = 1;
    }

    dim3 thr(256);
    dim3 wb(32, 8);
    int gsm = 2 * STAGE_HALVES * (int)sizeof(__nv_bfloat16);

    // 0: split x
    split_kernel<<<R_ * H_ / 256, thr>>>(x, xh, xl, R_ * H_);
    // 1: packed QKV weight split/transpose
    wconv3_kernel<<<dim3(32, 32, 3), wb>>>(Wq, Wk, Wv);
    // 2: beta
    beta_kernel<<<R_ / 4, 128>>>(x, Wb);
    // 3: QKV gemm (M=4096, N=3072, K=1024)  <- ncu target
    gemm_bf<<<dim3(3 * H_ / 128, R_ / 128), thr, gsm>>>(xh, xl, wh, wl, nullptr, qkv,
                                                        R_, 3 * H_, H_, 0);
    // convs
    conv_silu_kernel<<<R_ * H_ / 256, thr>>>(qkv, cq, qq, 3 * H_, 0);
    conv_silu_kernel<<<R_ * H_ / 256, thr>>>(qkv, ck, kk_, 3 * H_, H_);
    conv_silu_kernel<<<R_ * H_ / 256, thr>>>(qkv, cv, vv, 3 * H_, 2 * H_);
    // other weight splits
    wconv_kernel<<<dim3(MLPH_ / 32, GIN_ / 32), wb>>>(w1, w1h, w1l, GIN_, MLPH_);
    wconv_kernel<<<dim3(32, 32), wb>>>(Wo, woh, wol, H_, H_);
    // delta precompute
    precomp_kernel<<<B_ * NH_ * NCH_, thr,
                     (4 * 32 * RS + 2048) * sizeof(float)>>>();
    // scan
    scan_kernel<<<128, 512, 56832 * sizeof(float)>>>();
    // FIR
    fir_kernel<<<dim3(H_ / 64, B_ * L_ / 32), thr>>>(fsw, flw);
    // gate assembly + split
    gate_kernel<<<R_, thr>>>(x);
    split_kernel<<<(R_ * GIN_ + 255) / 256, thr>>>(gate, gh, gl, R_ * GIN_);
    // MLP1 (gelu fused)
    gemm_bf<<<dim3(MLPH_ / 128, R_ / 128), thr, gsm>>>(gh, gl, w1h, w1l, b1, mlp,
                                                       R_, MLPH_, GIN_, 1);
    mlp2_kernel<<<R_, 128>>>(w2, b2);
    // combine + RMSNorm
    combine_kernel<<<R_, thr>>>(lt, onw);
    // output projection (reuse xh/xl buffers for oc split)
    split_kernel<<<R_ * H_ / 256, thr>>>(oc, xh, xl, R_ * H_);
    gemm_bf<<<dim3(H_ / 128, R_ / 128), thr, gsm>>>(xh, xl, woh, wol, nullptr, out,
                                                    R_, H_, H_, 0);
}

// round 5
// speedup vs baseline: 3.6198x; 1.2655x over previous
#include <cuda_runtime.h>
#include <cuda_bf16.h>
#include <stdint.h>
#include <math.h>

#define B_   2
#define L_   2048
#define H_   1024
#define NH_  4
#define R_   (B_ * L_)       // 4096 rows
#define NCH_ 64              // chunks of 32 per sequence
#define GIN_ 1056
#define MLPH_ 2048

// ---------------- scratch ----------------
__device__ __align__(128) float g_qkv[(size_t)R_ * 3 * H_];
__device__ __align__(128) float g_qp[R_ * H_];     // u (fp32)
__device__ __align__(128) float g_vp[R_ * H_];     // delta_out
__device__ __align__(128) float g_q[R_ * H_];      // conv+silu q
__device__ __align__(128) float g_k[R_ * H_];      // conv+silu k
__device__ __align__(128) float g_v[R_ * H_];      // conv+silu v
__device__ __align__(128) float g_beta[R_ * NH_];
__device__ __align__(128) float g_fs[R_ * H_];
__device__ __align__(128) float g_fl[R_ * H_];
__device__ __align__(128) float g_gate[(size_t)R_ * GIN_];
__device__ __align__(128) float g_mlp[(size_t)R_ * MLPH_];
__device__ __align__(128) float g_logits[R_ * 16];
__device__ __align__(128) float g_oc[R_ * H_];

// bf16 hi/lo tiles for the scan (emitted by precomp)
__device__ __align__(128) __nv_bfloat16 g_tqh[R_ * H_], g_tql[R_ * H_];   // q normalized
__device__ __align__(128) __nv_bfloat16 g_twh[R_ * H_], g_twl[R_ * H_];   // w
__device__ __align__(128) __nv_bfloat16 g_tkth[(size_t)B_*NH_*NCH_*8192]; // kT [bh][n][256][32]
__device__ __align__(128) __nv_bfloat16 g_tktl[(size_t)B_*NH_*NCH_*8192];
__device__ __align__(128) __nv_bfloat16 g_tah[(size_t)B_*NH_*NCH_*1024];  // attn [bh][n][32][32]
__device__ __align__(128) __nv_bfloat16 g_tal[(size_t)B_*NH_*NCH_*1024];

// bf16 split weights [N][K] (QKV packed: 3072 x 1024)
__device__ __align__(128) __nv_bfloat16 g_wh[3 * H_ * H_], g_wl[3 * H_ * H_];
__device__ __align__(128) __nv_bfloat16 g_w1h[MLPH_ * GIN_], g_w1l[MLPH_ * GIN_];
__device__ __align__(128) __nv_bfloat16 g_woh[H_ * H_], g_wol[H_ * H_];
// bf16 split activations
__device__ __align__(128) __nv_bfloat16 g_xh[R_ * H_], g_xl[R_ * H_];
__device__ __align__(128) __nv_bfloat16 g_gh[(size_t)R_ * GIN_], g_gl[(size_t)R_ * GIN_];

// ---------------- cp.async helpers ----------------
__device__ __forceinline__ void cpa16(uint32_t dst, const void* src) {
    asm volatile("cp.async.cg.shared.global [%0], [%1], 16;" :: "r"(dst), "l"(src));
}
#define CPA_COMMIT asm volatile("cp.async.commit_group;")
#define SMEMU32(p) ((uint32_t)__cvta_generic_to_shared(p))

// ---------------- elementwise fp32 -> bf16 hi/lo split ----------------
__global__ void split_kernel(const float* __restrict__ A,
                             __nv_bfloat16* __restrict__ Ah,
                             __nv_bfloat16* __restrict__ Al, int n)
{
    int i = blockIdx.x * 256 + threadIdx.x;
    if (i < n) {
        float v = A[i];
        __nv_bfloat16 h = __float2bfloat16(v);
        Ah[i] = h;
        Al[i] = __float2bfloat16(v - __bfloat162float(h));
    }
}

// ---------------- weight transpose + split ----------------
__global__ void wconv_kernel(const float* __restrict__ W,
                             __nv_bfloat16* __restrict__ Th,
                             __nv_bfloat16* __restrict__ Tl, int K, int N)
{
    __shared__ float t[32][33];
    int k0 = blockIdx.y * 32, n0 = blockIdx.x * 32;
    int tx = threadIdx.x, ty = threadIdx.y;
    for (int i = ty; i < 32; i += 8)
        t[i][tx] = W[(size_t)(k0 + i) * N + n0 + tx];
    __syncthreads();
    for (int i = ty; i < 32; i += 8) {
        float v = t[tx][i];
        __nv_bfloat16 hi = __float2bfloat16(v);
        __nv_bfloat16 lo = __float2bfloat16(v - __bfloat162float(hi));
        size_t o = (size_t)(n0 + i) * K + k0 + tx;
        Th[o] = hi; Tl[o] = lo;
    }
}

__global__ void wconv3_kernel(const float* __restrict__ Wq,
                              const float* __restrict__ Wk,
                              const float* __restrict__ Wv)
{
    __shared__ float t[32][33];
    int z = blockIdx.z;
    const float* W = (z == 0) ? Wq : (z == 1) ? Wk : Wv;
    int k0 = blockIdx.y * 32, n0 = blockIdx.x * 32;
    int tx = threadIdx.x, ty = threadIdx.y;
    for (int i = ty; i < 32; i += 8)
        t[i][tx] = W[(size_t)(k0 + i) * H_ + n0 + tx];
    __syncthreads();
    size_t base = (size_t)z * H_ * H_;
    for (int i = ty; i < 32; i += 8) {
        float v = t[tx][i];
        __nv_bfloat16 hi = __float2bfloat16(v);
        __nv_bfloat16 lo = __float2bfloat16(v - __bfloat162float(hi));
        size_t o = base + (size_t)(n0 + i) * H_ + k0 + tx;
        g_wh[o] = hi; g_wl[o] = lo;
    }
}

// ---------------- tensor-core GEMM (validated round-4 version) ----------------
#define MMA16816(d, a, b0, b1) \
  asm volatile("mma.sync.aligned.m16n8k16.row.col.f32.bf16.bf16.f32 " \
    "{%0,%1,%2,%3}, {%4,%5,%6,%7}, {%8,%9}, {%0,%1,%2,%3};" \
    : "+f"(d[0]), "+f"(d[1]), "+f"(d[2]), "+f"(d[3]) \
    : "r"(a[0]), "r"(a[1]), "r"(a[2]), "r"(a[3]), "r"(b0), "r"(b1))

#define ASTR 40
#define STAGE_HALVES (4 * 128 * ASTR)

__global__ __launch_bounds__(256) void gemm_bf(
    const __nv_bfloat16* __restrict__ Ahg, const __nv_bfloat16* __restrict__ Alg,
    const __nv_bfloat16* __restrict__ Bhg, const __nv_bfloat16* __restrict__ Blg,
    const float* __restrict__ bias, float* __restrict__ C,
    int M, int N, int K, int act)
{
    extern __shared__ __nv_bfloat16 smh[];
    int tid = threadIdx.x;
    int row0 = blockIdx.y * 128, col0 = blockIdx.x * 128;
    int wid = tid >> 5, lane = tid & 31;
    int wm = (wid >> 1) * 32, wn = (wid & 1) * 64;
    int g = lane >> 2, t = lane & 3;

    float acc[2][8][4];
#pragma unroll
    for (int i = 0; i < 2; i++)
#pragma unroll
        for (int j = 0; j < 8; j++)
#pragma unroll
            for (int q = 0; q < 4; q++) acc[i][j][q] = 0.f;

    const __nv_bfloat16* gsrc[4] = {Ahg, Alg, Bhg, Blg};
    int gr0[4] = {row0, row0, col0, col0};

    auto load_stage = [&](int s, int k0) {
        __nv_bfloat16* sp = smh + s * STAGE_HALVES;
#pragma unroll
        for (int a = 0; a < 4; a++) {
#pragma unroll
            for (int q = 0; q < 2; q++) {
                int c = tid * 2 + q;
                int r = c >> 2, seg = c & 3;
                uint32_t d = SMEMU32(sp + a * 128 * ASTR + r * ASTR + seg * 8);
                cpa16(d, gsrc[a] + (size_t)(gr0[a] + r) * K + k0 + seg * 8);
            }
        }
        CPA_COMMIT;
    };

    load_stage(0, 0);
    int nk = K / 32;
    for (int ki = 0; ki < nk; ki++) {
        if (ki + 1 < nk) {
            load_stage((ki + 1) & 1, (ki + 1) * 32);
            asm volatile("cp.async.wait_group 1;");
        } else {
            asm volatile("cp.async.wait_group 0;");
        }
        __syncthreads();
        __nv_bfloat16* sp = smh + (ki & 1) * STAGE_HALVES;
        __nv_bfloat16* Ah = sp;
        __nv_bfloat16* Al = sp + 128 * ASTR;
        __nv_bfloat16* Bh = sp + 2 * 128 * ASTR;
        __nv_bfloat16* Bl = sp + 3 * 128 * ASTR;
#pragma unroll
        for (int ks = 0; ks < 2; ks++) {
            int ko = ks * 16;
            uint32_t afh[2][4], afl[2][4];
#pragma unroll
            for (int mi = 0; mi < 2; mi++) {
                int mb = wm + mi * 16;
                afh[mi][0] = *(const uint32_t*)&Ah[(mb + g)     * ASTR + ko + 2 * t];
                afh[mi][1] = *(const uint32_t*)&Ah[(mb + 8 + g) * ASTR + ko + 2 * t];
                afh[mi][2] = *(const uint32_t*)&Ah[(mb + g)     * ASTR + ko + 2 * t + 8];
                afh[mi][3] = *(const uint32_t*)&Ah[(mb + 8 + g) * ASTR + ko + 2 * t + 8];
                afl[mi][0] = *(const uint32_t*)&Al[(mb + g)     * ASTR + ko + 2 * t];
                afl[mi][1] = *(const uint32_t*)&Al[(mb + 8 + g) * ASTR + ko + 2 * t];
                afl[mi][2] = *(const uint32_t*)&Al[(mb + g)     * ASTR + ko + 2 * t + 8];
                afl[mi][3] = *(const uint32_t*)&Al[(mb + 8 + g) * ASTR + ko + 2 * t + 8];
            }
#pragma unroll
            for (int ni = 0; ni < 8; ni++) {
                int nb = wn + ni * 8;
                uint32_t bh0 = *(const uint32_t*)&Bh[(nb + g) * ASTR + ko + 2 * t];
                uint32_t bh1 = *(const uint32_t*)&Bh[(nb + g) * ASTR + ko + 2 * t + 8];
                uint32_t bl0 = *(const uint32_t*)&Bl[(nb + g) * ASTR + ko + 2 * t];
                uint32_t bl1 = *(const uint32_t*)&Bl[(nb + g) * ASTR + ko + 2 * t + 8];
#pragma unroll
                for (int mi = 0; mi < 2; mi++) {
                    MMA16816(acc[mi][ni], afh[mi], bh0, bh1);
                    MMA16816(acc[mi][ni], afl[mi], bh0, bh1);
                    MMA16816(acc[mi][ni], afh[mi], bl0, bl1);
                }
            }
        }
        __syncthreads();
    }

#pragma unroll
    for (int mi = 0; mi < 2; mi++)
#pragma unroll
        for (int ni = 0; ni < 8; ni++) {
            int r = row0 + wm + mi * 16 + g;
            int c = col0 + wn + ni * 8 + 2 * t;
            float v[4];
#pragma unroll
            for (int q = 0; q < 4; q++) {
                float x = acc[mi][ni][q];
                if (bias) x += bias[c + (q & 1)];
                if (act == 1) x = 0.5f * x * (1.f + erff(x * 0.70710678118654752f));
                v[q] = x;
            }
            *(float2*)(C + (size_t)r * N + c)       = make_float2(v[0], v[1]);
            *(float2*)(C + (size_t)(r + 8) * N + c) = make_float2(v[2], v[3]);
        }
}

// ---------------- beta ----------------
__global__ void beta_kernel(const float* __restrict__ x, const float* __restrict__ Wb)
{
    int r = blockIdx.x * 4 + (threadIdx.x >> 5);
    int lane = threadIdx.x & 31;
    float acc0 = 0, acc1 = 0, acc2 = 0, acc3 = 0;
    const float* xr = x + (size_t)r * H_;
    for (int kk = lane; kk < H_; kk += 32) {
        float xv = xr[kk];
        const float* w = Wb + kk * 4;
        acc0 += xv * w[0]; acc1 += xv * w[1]; acc2 += xv * w[2]; acc3 += xv * w[3];
    }
#pragma unroll
    for (int off = 16; off; off >>= 1) {
        acc0 += __shfl_down_sync(~0u, acc0, off);
        acc1 += __shfl_down_sync(~0u, acc1, off);
        acc2 += __shfl_down_sync(~0u, acc2, off);
        acc3 += __shfl_down_sync(~0u, acc3, off);
    }
    if (lane == 0) {
        g_beta[r * 4 + 0] = 1.f / (1.f + expf(-acc0));
        g_beta[r * 4 + 1] = 1.f / (1.f + expf(-acc1));
        g_beta[r * 4 + 2] = 1.f / (1.f + expf(-acc2));
        g_beta[r * 4 + 3] = 1.f / (1.f + expf(-acc3));
    }
}

// ---------------- causal conv K=4 + silu ----------------
__global__ void conv_silu_kernel(const float* __restrict__ src,
                                 const float* __restrict__ w,
                                 float* __restrict__ dst, int srcStride, int srcOff)
{
    int tid = blockIdx.x * blockDim.x + threadIdx.x;
    int c = tid & (H_ - 1);
    int r = tid >> 10;
    int b = r >> 11;
    int l = r & (L_ - 1);
    const float* wc = w + c * 4;
    float acc = 0.f;
#pragma unroll
    for (int j = 0; j < 4; j++) {
        int ll = l - 3 + j;
        if (ll >= 0) acc += src[(size_t)(b * L_ + ll) * srcStride + srcOff + c] * wc[j];
    }
    dst[tid] = acc / (1.f + expf(-acc));
}

// ---------------- delta precompute: emits bf16 hi/lo tiles ----------------
#define RS 257
__global__ __launch_bounds__(256) void precomp_kernel()
{
    extern __shared__ float sm[];
    float* Qs = sm;
    float* Ks = Qs + 32 * RS;
    float* KB = Ks + 32 * RS;
    float* VB = KB + 32 * RS;
    float* Am = VB + 32 * RS;
    float* Tm = Am + 1024;
    __shared__ float rbeta[32], qn_s[32], kn_s[32];

    int bhn = blockIdx.x;
    int n = bhn % NCH_; int bh = bhn / NCH_;
    int b = bh >> 2, h = bh & 3;
    int l0 = n * 32;
    int tid = threadIdx.x, wi = tid >> 5, lane = tid & 31;

    for (int e = tid; e < 8192; e += 256) {
        int i = e >> 8, d = e & 255;
        size_t gi = ((size_t)(b * L_ + l0 + i) << 10) + h * 256 + d;
        Qs[i * RS + d] = g_q[gi];
        Ks[i * RS + d] = g_k[gi];
    }
    if (tid < 32) rbeta[tid] = g_beta[(b * L_ + l0 + tid) * 4 + h];
    __syncthreads();

    for (int rr = wi; rr < 32; rr += 8) {
        float sq = 0, sk = 0;
        for (int d = lane; d < 256; d += 32) {
            float a = Qs[rr * RS + d]; sq += a * a;
            float c = Ks[rr * RS + d]; sk += c * c;
        }
#pragma unroll
        for (int off = 16; off; off >>= 1) {
            sq += __shfl_down_sync(~0u, sq, off);
            sk += __shfl_down_sync(~0u, sk, off);
        }
        if (lane == 0) { qn_s[rr] = rsqrtf(sq + 1e-6f); kn_s[rr] = rsqrtf(sk + 1e-6f); }
    }
    __syncthreads();

    for (int e = tid; e < 8192; e += 256) {
        int i = e >> 8, d = e & 255;
        size_t gi = ((size_t)(b * L_ + l0 + i) << 10) + h * 256 + d;
        float qv = Qs[i * RS + d] * qn_s[i]; Qs[i * RS + d] = qv;
        float kv = Ks[i * RS + d] * kn_s[i]; Ks[i * RS + d] = kv;
        KB[i * RS + d] = kv * rbeta[i];
        VB[i * RS + d] = g_v[gi] * rbeta[i];
        __nv_bfloat16 qh = __float2bfloat16(qv);
        g_tqh[gi] = qh;
        g_tql[gi] = __float2bfloat16(qv - __bfloat162float(qh));
    }
    __syncthreads();

    // kT bf16 tiles [256][32]
    {
        size_t ckb = ((size_t)bh * NCH_ + n) * 8192;
        for (int e = tid; e < 8192; e += 256) {
            int d = e >> 5, i = e & 31;
            float kv = Ks[i * RS + d];
            __nv_bfloat16 kh = __float2bfloat16(kv);
            g_tkth[ckb + e] = kh;
            g_tktl[ckb + e] = __float2bfloat16(kv - __bfloat162float(kh));
        }
    }

    for (int e = tid; e < 1024; e += 256) {
        int i = e >> 5, j = e & 31;
        float s = 0.f;
        if (j < i) {
            const float* a = KB + i * RS; const float* c = Ks + j * RS;
            for (int d = 0; d < 256; d++) s += a[d] * c[d];
        }
        Am[e] = s;
    }
    __syncthreads();

    if (wi == 0) {
        int j = lane;
        for (int i = 0; i < 32; i++) {
            float val = (i == j) ? 1.f : 0.f;
            for (int m = j; m < i; m++) val -= Am[i * 32 + m] * Tm[m * 32 + j];
            Tm[i * 32 + j] = val;
            __syncwarp();
        }
    }
    __syncthreads();

    // attn = tril(Qs @ Ks^T) -> bf16 hi/lo
    {
        size_t ab = ((size_t)bh * NCH_ + n) * 1024;
        for (int e = tid; e < 1024; e += 256) {
            int i = e >> 5, j = e & 31;
            float s = 0.f;
            if (j <= i) {
                const float* a = Qs + i * RS; const float* c = Ks + j * RS;
                for (int d = 0; d < 256; d++) s += a[d] * c[d];
            }
            __nv_bfloat16 hv = __float2bfloat16(s);
            g_tah[ab + e] = hv;
            g_tal[ab + e] = __float2bfloat16(s - __bfloat162float(hv));
        }
    }

    // u = T @ VB (fp32), w = T @ KB (bf16 hi/lo)
    for (int e = tid; e < 8192; e += 256) {
        int i = e >> 8, d = e & 255;
        float su = 0, sw = 0;
        const float* tr = Tm + i * 32;
#pragma unroll
        for (int m = 0; m < 32; m++) {
            float t = tr[m];
            su += t * VB[m * RS + d];
            sw += t * KB[m * RS + d];
        }
        size_t gi = ((size_t)(b * L_ + l0 + i) << 10) + h * 256 + d;
        g_qp[gi] = su;
        __nv_bfloat16 wh_ = __float2bfloat16(sw);
        g_twh[gi] = wh_;
        g_twl[gi] = __float2bfloat16(sw - __bfloat162float(wh_));
    }
}

// ---------------- tensor-core scan ----------------
// grid 128 (8 bh x 16 dv-slices of 16), 256 threads (8 warps), 228352 B smem.
// smem map (bytes):
//   0      S fp32 [256][16]
//   16384  U2 fp32 [32][16]
//   18432  SbTh [16][264], 26880 SbTl
//   35328  U2Th [16][40],  36608 U2Tl
//   37888  KTh [256][40],  58368 KTl
//   78848  stage0 (74752): Wh,Wl,Qh,Ql [32][264] x4; U fp32 [32][16]; Ath,Atl [32][40]
//   153600 stage1
#define SC_SMEM 228352
#define STG_OFF 78848
#define STG_SZ  74752

__global__ __launch_bounds__(256) void scan_kernel()
{
    extern __shared__ char sc[];
    float* S  = (float*)sc;
    float* U2 = (float*)(sc + 16384);
    __nv_bfloat16* SbTh = (__nv_bfloat16*)(sc + 18432);
    __nv_bfloat16* SbTl = (__nv_bfloat16*)(sc + 26880);
    __nv_bfloat16* U2Th = (__nv_bfloat16*)(sc + 35328);
    __nv_bfloat16* U2Tl = (__nv_bfloat16*)(sc + 36608);
    __nv_bfloat16* KTh  = (__nv_bfloat16*)(sc + 37888);
    __nv_bfloat16* KTl  = (__nv_bfloat16*)(sc + 58368);

    int blk = blockIdx.x;
    int bh = blk >> 4, slice = blk & 15;
    int b = bh >> 2, h = bh & 3;
    int tid = threadIdx.x;
    int wi = tid >> 5, lane = tid & 31;
    int g = lane >> 2, t4 = lane & 3;
    int dvb = h * 256 + slice * 16;

    for (int e = tid; e < 4096; e += 256) S[e] = 0.f;
    for (int e = tid; e < 16 * 264; e += 256) {
        SbTh[e] = __float2bfloat16(0.f);
        SbTl[e] = __float2bfloat16(0.f);
    }

    auto issue_main = [&](int n, int buf) {
        char* sp = sc + STG_OFF + buf * STG_SZ;
        __nv_bfloat16* dsts[4] = {
            (__nv_bfloat16*)sp, (__nv_bfloat16*)(sp + 16896),
            (__nv_bfloat16*)(sp + 33792), (__nv_bfloat16*)(sp + 50688)};
        const __nv_bfloat16* srcs[4] = {g_twh, g_twl, g_tqh, g_tql};
        int row0 = b * L_ + n * 32;
#pragma unroll
        for (int it = 0; it < 16; it++) {
            int c = tid + it * 256;
            int a = c >> 10, rem = c & 1023;
            int r = rem >> 5, s = rem & 31;
            cpa16(SMEMU32(dsts[a] + r * 264 + s * 8),
                  srcs[a] + ((size_t)(row0 + r) << 10) + h * 256 + s * 8);
        }
        if (tid < 128) {
            int r = tid >> 2, s = tid & 3;
            float* Uf = (float*)(sp + 67584);
            cpa16(SMEMU32(Uf + r * 16 + s * 4),
                  g_qp + ((size_t)(row0 + r) << 10) + dvb + s * 4);
        }
        {
            int a = tid >> 7, rem = tid & 127;
            int r = rem >> 2, s = rem & 3;
            __nv_bfloat16* dst = (__nv_bfloat16*)(sp + (a ? 72192 : 69632));
            const __nv_bfloat16* src = a ? g_tal : g_tah;
            cpa16(SMEMU32(dst + r * 40 + s * 8),
                  src + ((size_t)bh * NCH_ + n) * 1024 + r * 32 + s * 8);
        }
        CPA_COMMIT;
    };

    auto issue_kT = [&](int n) {
        size_t base = ((size_t)bh * NCH_ + n) * 8192;
#pragma unroll
        for (int it = 0; it < 8; it++) {
            int c = tid + it * 256;
            int a = c >> 10, rem = c & 1023;
            int r = rem >> 2, s = rem & 3;
            __nv_bfloat16* dst = a ? KTl : KTh;
            const __nv_bfloat16* src = a ? g_tktl : g_tkth;
            cpa16(SMEMU32(dst + r * 40 + s * 8), src + base + r * 32 + s * 8);
        }
        CPA_COMMIT;
    };

    issue_main(0, 0);
    issue_kT(0);
    int buf = 0;

#pragma unroll 1
    for (int n = 0; n < NCH_; n++) {
        asm volatile("cp.async.wait_group 0;");
        if (n + 1 < NCH_) issue_main(n + 1, buf ^ 1);
        __syncthreads();

        char* sp = sc + STG_OFF + buf * STG_SZ;
        const __nv_bfloat16* Wh = (const __nv_bfloat16*)sp;
        const __nv_bfloat16* Wl = (const __nv_bfloat16*)(sp + 16896);
        const __nv_bfloat16* Qh = (const __nv_bfloat16*)(sp + 33792);
        const __nv_bfloat16* Ql = (const __nv_bfloat16*)(sp + 50688);
        const float* Uf = (const float*)(sp + 67584);
        const __nv_bfloat16* Ath = (const __nv_bfloat16*)(sp + 69632);
        const __nv_bfloat16* Atl = (const __nv_bfloat16*)(sp + 72192);

        // phase 1: warps 0-3 compute w@S; warps 4-7 compute q@S (same tiling)
        float c0[4] = {0,0,0,0}, c1[4] = {0,0,0,0}, c2[4] = {0,0,0,0};
        int w4 = wi & 3;
        int m0 = (w4 >> 1) * 16, n0 = (w4 & 1) * 8;
        const __nv_bfloat16* Ah = (wi < 4) ? Wh : Qh;
        const __nv_bfloat16* Al = (wi < 4) ? Wl : Ql;
#pragma unroll
        for (int kk = 0; kk < 16; kk++) {
            int ka = kk * 16 + 2 * t4;
            uint32_t ah[4], al[4];
            ah[0] = *(const uint32_t*)&Ah[(m0 + g) * 264 + ka];
            ah[1] = *(const uint32_t*)&Ah[(m0 + 8 + g) * 264 + ka];
            ah[2] = *(const uint32_t*)&Ah[(m0 + g) * 264 + ka + 8];
            ah[3] = *(const uint32_t*)&Ah[(m0 + 8 + g) * 264 + ka + 8];
            al[0] = *(const uint32_t*)&Al[(m0 + g) * 264 + ka];
            al[1] = *(const uint32_t*)&Al[(m0 + 8 + g) * 264 + ka];
            al[2] = *(const uint32_t*)&Al[(m0 + g) * 264 + ka + 8];
            al[3] = *(const uint32_t*)&Al[(m0 + 8 + g) * 264 + ka + 8];
            uint32_t bh0 = *(const uint32_t*)&SbTh[(n0 + g) * 264 + ka];
            uint32_t bh1 = *(const uint32_t*)&SbTh[(n0 + g) * 264 + ka + 8];
            uint32_t bl0 = *(const uint32_t*)&SbTl[(n0 + g) * 264 + ka];
            uint32_t bl1 = *(const uint32_t*)&SbTl[(n0 + g) * 264 + ka + 8];
            MMA16816(c0, ah, bh0, bh1);
            MMA16816(c1, al, bh0, bh1);
            MMA16816(c2, ah, bl0, bl1);
        }
        if (wi < 4) {
            U2[(m0 + g) * 16 + n0 + 2 * t4]         = Uf[(m0 + g) * 16 + n0 + 2 * t4]         - (c0[0] + c1[0] + c2[0]);
            U2[(m0 + g) * 16 + n0 + 2 * t4 + 1]     = Uf[(m0 + g) * 16 + n0 + 2 * t4 + 1]     - (c0[1] + c1[1] + c2[1]);
            U2[(m0 + 8 + g) * 16 + n0 + 2 * t4]     = Uf[(m0 + 8 + g) * 16 + n0 + 2 * t4]     - (c0[2] + c1[2] + c2[2]);
            U2[(m0 + 8 + g) * 16 + n0 + 2 * t4 + 1] = Uf[(m0 + 8 + g) * 16 + n0 + 2 * t4 + 1] - (c0[3] + c1[3] + c2[3]);
        }
        __syncthreads();

        // build u2T bf16 hi/lo
#pragma unroll
        for (int q2 = 0; q2 < 2; q2++) {
            int e = tid + q2 * 256;
            int i2 = e >> 4, j2 = e & 15;
            float v = U2[i2 * 16 + j2];
            __nv_bfloat16 hv = __float2bfloat16(v);
            U2Th[j2 * 40 + i2] = hv;
            U2Tl[j2 * 40 + i2] = __float2bfloat16(v - __bfloat162float(hv));
        }
        __syncthreads();

        // phase 2 (warps 4-7): o = q@S + attn@u2, store
        if (wi >= 4) {
#pragma unroll
            for (int kk = 0; kk < 2; kk++) {
                int ka = kk * 16 + 2 * t4;
                uint32_t ah[4], al[4];
                ah[0] = *(const uint32_t*)&Ath[(m0 + g) * 40 + ka];
                ah[1] = *(const uint32_t*)&Ath[(m0 + 8 + g) * 40 + ka];
                ah[2] = *(const uint32_t*)&Ath[(m0 + g) * 40 + ka + 8];
                ah[3] = *(const uint32_t*)&Ath[(m0 + 8 + g) * 40 + ka + 8];
                al[0] = *(const uint32_t*)&Atl[(m0 + g) * 40 + ka];
                al[1] = *(const uint32_t*)&Atl[(m0 + 8 + g) * 40 + ka];
                al[2] = *(const uint32_t*)&Atl[(m0 + g) * 40 + ka + 8];
                al[3] = *(const uint32_t*)&Atl[(m0 + 8 + g) * 40 + ka + 8];
                uint32_t bh0 = *(const uint32_t*)&U2Th[(n0 + g) * 40 + ka];
                uint32_t bh1 = *(const uint32_t*)&U2Th[(n0 + g) * 40 + ka + 8];
                uint32_t bl0 = *(const uint32_t*)&U2Tl[(n0 + g) * 40 + ka];
                uint32_t bl1 = *(const uint32_t*)&U2Tl[(n0 + g) * 40 + ka + 8];
                MMA16816(c0, ah, bh0, bh1);
                MMA16816(c1, al, bh0, bh1);
                MMA16816(c2, ah, bl0, bl1);
            }
            size_t ob = ((size_t)(b * L_ + n * 32) << 10) + dvb + n0 + 2 * t4;
            *(float2*)(g_vp + ob + ((size_t)(m0 + g) << 10)) =
                make_float2(c0[0] + c1[0] + c2[0], c0[1] + c1[1] + c2[1]);
            *(float2*)(g_vp + ob + ((size_t)(m0 + 8 + g) << 10)) =
                make_float2(c0[2] + c1[2] + c2[2], c0[3] + c1[3] + c2[3]);
        }

        // phase 3 (all warps): S += kT @ u2
#pragma unroll
        for (int mm = 0; mm < 2; mm++)
#pragma unroll
        for (int nn = 0; nn < 2; nn++) {
            int m0p = (wi * 2 + mm) * 16, n0p = nn * 8;
            float d0[4];
            float2 s01 = *(float2*)(S + (m0p + g) * 16 + n0p + 2 * t4);
            float2 s23 = *(float2*)(S + (m0p + 8 + g) * 16 + n0p + 2 * t4);
            d0[0] = s01.x; d0[1] = s01.y; d0[2] = s23.x; d0[3] = s23.y;
#pragma unroll
            for (int kk = 0; kk < 2; kk++) {
                int ka = kk * 16 + 2 * t4;
                uint32_t ah[4], al[4];
                ah[0] = *(const uint32_t*)&KTh[(m0p + g) * 40 + ka];
                ah[1] = *(const uint32_t*)&KTh[(m0p + 8 + g) * 40 + ka];
                ah[2] = *(const uint32_t*)&KTh[(m0p + g) * 40 + ka + 8];
                ah[3] = *(const uint32_t*)&KTh[(m0p + 8 + g) * 40 + ka + 8];
                al[0] = *(const uint32_t*)&KTl[(m0p + g) * 40 + ka];
                al[1] = *(const uint32_t*)&KTl[(m0p + 8 + g) * 40 + ka];
                al[2] = *(const uint32_t*)&KTl[(m0p + g) * 40 + ka + 8];
                al[3] = *(const uint32_t*)&KTl[(m0p + 8 + g) * 40 + ka + 8];
                uint32_t bh0 = *(const uint32_t*)&U2Th[(n0p + g) * 40 + ka];
                uint32_t bh1 = *(const uint32_t*)&U2Th[(n0p + g) * 40 + ka + 8];
                uint32_t bl0 = *(const uint32_t*)&U2Tl[(n0p + g) * 40 + ka];
                uint32_t bl1 = *(const uint32_t*)&U2Tl[(n0p + g) * 40 + ka + 8];
                MMA16816(d0, ah, bh0, bh1);
                MMA16816(d0, al, bh0, bh1);
                MMA16816(d0, ah, bl0, bl1);
            }
            *(float2*)(S + (m0p + g) * 16 + n0p + 2 * t4)     = make_float2(d0[0], d0[1]);
            *(float2*)(S + (m0p + 8 + g) * 16 + n0p + 2 * t4) = make_float2(d0[2], d0[3]);
        }
        __syncthreads();

        if (n + 1 < NCH_) issue_kT(n + 1);

        // rebuild SbT from S
        {
            int k = tid;
#pragma unroll
            for (int j = 0; j < 16; j++) {
                float v = S[k * 16 + j];
                __nv_bfloat16 hv = __float2bfloat16(v);
                SbTh[j * 264 + k] = hv;
                SbTl[j * 264 + k] = __float2bfloat16(v - __bfloat162float(hv));
            }
        }
        __syncthreads();
        buf ^= 1;
    }
}

// ---------------- FIR convs ----------------
__global__ __launch_bounds__(256) void fir_kernel(const float* __restrict__ ws,
                                                  const float* __restrict__ wl)
{
    __shared__ float vt[94][64];
    __shared__ float wls[64 * 63];
    __shared__ float wss[64 * 3];
    int cb = blockIdx.x;
    int lb = blockIdx.y;
    int b = lb >> 6;
    int l0 = (lb & 63) * 32;
    int c0 = cb * 64;
    int tid = threadIdx.x;

    for (int e = tid; e < 94 * 64; e += 256) {
        int rr = e >> 6, cc = e & 63;
        int l = l0 - 62 + rr;
        vt[rr][cc] = (l >= 0) ? g_v[((size_t)(b * L_ + l) << 10) + c0 + cc] : 0.f;
    }
    for (int e = tid; e < 64 * 63; e += 256) wls[e] = wl[(size_t)c0 * 63 + e];
    for (int e = tid; e < 64 * 3; e += 256)  wss[e] = ws[(size_t)c0 * 3 + e];
    __syncthreads();

    for (int e = tid; e < 32 * 64; e += 256) {
        int i = e >> 6, cc = e & 63;
        float aL = 0.f, aS = 0.f;
        const float* wlr = wls + cc * 63;
#pragma unroll 9
        for (int j = 0; j < 63; j++) aL += vt[i + j][cc] * wlr[j];
        const float* wsr = wss + cc * 3;
#pragma unroll
        for (int j = 0; j < 3; j++) aS += vt[i + 60 + j][cc] * wsr[j];
        size_t gi = ((size_t)(b * L_ + l0 + i) << 10) + c0 + cc;
        g_fl[gi] = aL;
        g_fs[gi] = aS;
    }
}

// ---------------- gate input ----------------
__global__ void gate_kernel(const float* __restrict__ x)
{
    int r = blockIdx.x, tid = threadIdx.x;
    float* grow = g_gate + (size_t)r * GIN_;
    const float* xr = x + (size_t)r * H_;
    for (int e = tid; e < H_; e += 256) grow[e] = xr[e];

    int wi = tid >> 5, lane = tid & 31;
    for (int p = wi; p < 16; p += 8) {
        int br = p >> 2, h = p & 3;
        const float* src = (br == 0 ? g_fs : br == 1 ? g_fl : br == 2 ? g_vp : g_v)
                           + ((size_t)r << 10) + h * 256;
        float s = 0, s2 = 0;
        for (int d = lane; d < 256; d += 32) { float t = src[d]; s += t; s2 += t * t; }
#pragma unroll
        for (int off = 16; off; off >>= 1) {
            s += __shfl_down_sync(~0u, s, off);
            s2 += __shfl_down_sync(~0u, s2, off);
        }
        if (lane == 0) {
            float mean = s * (1.f / 256.f);
            float var = s2 * (1.f / 256.f) - mean * mean;
            grow[1024 + br * 8 + h] = mean;
            grow[1024 + br * 8 + 4 + h] = sqrtf(fmaxf(var, 1e-6f));
        }
    }
}

// ---------------- MLP2 ----------------
__global__ void mlp2_kernel(const float* __restrict__ w2, const float* __restrict__ b2)
{
    int r = blockIdx.x, tid = threadIdx.x;
    float acc[16];
#pragma unroll
    for (int o = 0; o < 16; o++) acc[o] = 0.f;
    const float* hr = g_mlp + (size_t)r * MLPH_;
    for (int kk = tid; kk < MLPH_; kk += 128) {
        float hv = hr[kk];
        const float4* wr = (const float4*)(w2 + (size_t)kk * 16);
        float4 w0 = wr[0], w1 = wr[1], w2v = wr[2], w3 = wr[3];
        acc[0] += hv * w0.x; acc[1] += hv * w0.y; acc[2] += hv * w0.z; acc[3] += hv * w0.w;
        acc[4] += hv * w1.x; acc[5] += hv * w1.y; acc[6] += hv * w1.z; acc[7] += hv * w1.w;
        acc[8] += hv * w2v.x; acc[9] += hv * w2v.y; acc[10] += hv * w2v.z; acc[11] += hv * w2v.w;
        acc[12] += hv * w3.x; acc[13] += hv * w3.y; acc[14] += hv * w3.z; acc[15] += hv * w3.w;
    }
    __shared__ float part[4][16];
    int wi = tid >> 5, lane = tid & 31;
#pragma unroll
    for (int o = 0; o < 16; o++) {
        float v = acc[o];
#pragma unroll
        for (int off = 16; off; off >>= 1) v += __shfl_down_sync(~0u, v, off);
        if (lane == 0) part[wi][o] = v;
    }
    __syncthreads();
    if (tid < 16)
        g_logits[r * 16 + tid] =
            part[0][tid] + part[1][tid] + part[2][tid] + part[3][tid] + b2[tid];
}

// ---------------- combine + RMSNorm ----------------
__global__ void combine_kernel(const float* __restrict__ ltemp,
                               const float* __restrict__ onw)
{
    int r = blockIdx.x, tid = threadIdx.x;
    __shared__ float red[256];
    const float* lg = g_logits + r * 16;
#pragma unroll 1
    for (int h = 0; h < 4; h++) {
        float temp = log1pf(expf(ltemp[h])) + 1e-4f;
        float l0 = lg[h * 4 + 0] / temp, l1 = lg[h * 4 + 1] / temp;
        float l2 = lg[h * 4 + 2] / temp, l3 = lg[h * 4 + 3] / temp;
        float mx = fmaxf(fmaxf(l0, l1), fmaxf(l2, l3));
        float e0 = expf(l0 - mx), e1 = expf(l1 - mx), e2 = expf(l2 - mx), e3 = expf(l3 - mx);
        float inv = 1.f / (e0 + e1 + e2 + e3);
        size_t idx = ((size_t)r << 10) + h * 256 + tid;
        float ov = (e0 * g_fs[idx] + e1 * g_fl[idx] + e2 * g_vp[idx] + e3 * g_v[idx]) * inv;
        red[tid] = ov * ov;
        __syncthreads();
        for (int s = 128; s; s >>= 1) { if (tid < s) red[tid] += red[tid + s]; __syncthreads(); }
        float scale = rsqrtf(red[0] * (1.f / 256.f) + 1e-5f);
        g_oc[idx] = ov * scale * onw[tid];
        __syncthreads();
    }
}

// ---------------- launch ----------------
extern "C" void kernel_launch(void* const* d_in, const int* in_sizes, int n_in,
                              void* d_out, int out_size)
{
    const float* x   = (const float*)d_in[0];
    const float* Wq  = (const float*)d_in[1];
    const float* Wk  = (const float*)d_in[2];
    const float* Wv  = (const float*)d_in[3];
    const float* Wb  = (const float*)d_in[4];
    const float* cq  = (const float*)d_in[5];
    const float* ck  = (const float*)d_in[6];
    const float* cv  = (const float*)d_in[7];
    const float* fsw = (const float*)d_in[8];
    const float* flw = (const float*)d_in[9];
    const float* w1  = (const float*)d_in[10];
    const float* b1  = (const float*)d_in[11];
    const float* w2  = (const float*)d_in[12];
    const float* b2  = (const float*)d_in[13];
    const float* lt  = (const float*)d_in[14];
    const float* onw = (const float*)d_in[15];
    const float* Wo  = (const float*)d_in[16];
    float* out = (float*)d_out;

    void* p;
    float *qkv, *qq, *kk_, *vv, *gate, *mlp, *oc;
    __nv_bfloat16 *wh, *wl, *w1h, *w1l, *woh, *wol, *xh, *xl, *gh, *gl;
    cudaGetSymbolAddress(&p, g_qkv); qkv = (float*)p;
    cudaGetSymbolAddress(&p, g_q);   qq = (float*)p;
    cudaGetSymbolAddress(&p, g_k);   kk_ = (float*)p;
    cudaGetSymbolAddress(&p, g_v);   vv = (float*)p;
    cudaGetSymbolAddress(&p, g_gate); gate = (float*)p;
    cudaGetSymbolAddress(&p, g_mlp); mlp = (float*)p;
    cudaGetSymbolAddress(&p, g_oc);  oc = (float*)p;
    cudaGetSymbolAddress(&p, g_wh);  wh = (__nv_bfloat16*)p;
    cudaGetSymbolAddress(&p, g_wl);  wl = (__nv_bfloat16*)p;
    cudaGetSymbolAddress(&p, g_w1h); w1h = (__nv_bfloat16*)p;
    cudaGetSymbolAddress(&p, g_w1l); w1l = (__nv_bfloat16*)p;
    cudaGetSymbolAddress(&p, g_woh); woh = (__nv_bfloat16*)p;
    cudaGetSymbolAddress(&p, g_wol); wol = (__nv_bfloat16*)p;
    cudaGetSymbolAddress(&p, g_xh);  xh = (__nv_bfloat16*)p;
    cudaGetSymbolAddress(&p, g_xl);  xl = (__nv_bfloat16*)p;
    cudaGetSymbolAddress(&p, g_gh);  gh = (__nv_bfloat16*)p;
    cudaGetSymbolAddress(&p, g_gl);  gl = (__nv_bfloat16*)p;

    static int attr_done = 0;
    if (!attr_done) {
        cudaFuncSetAttribute(gemm_bf, cudaFuncAttributeMaxDynamicSharedMemorySize,
                             2 * STAGE_HALVES * (int)sizeof(__nv_bfloat16));
        cudaFuncSetAttribute(precomp_kernel, cudaFuncAttributeMaxDynamicSharedMemorySize,
                             (4 * 32 * RS + 2048) * (int)sizeof(float));
        cudaFuncSetAttribute(scan_kernel, cudaFuncAttributeMaxDynamicSharedMemorySize,
                             SC_SMEM);
        attr_done = 1;
    }

    dim3 thr(256);
    dim3 wb(32, 8);
    int gsm = 2 * STAGE_HALVES * (int)sizeof(__nv_bfloat16);

    split_kernel<<<R_ * H_ / 256, thr>>>(x, xh, xl, R_ * H_);
    wconv3_kernel<<<dim3(32, 32, 3), wb>>>(Wq, Wk, Wv);
    beta_kernel<<<R_ / 4, 128>>>(x, Wb);
    gemm_bf<<<dim3(3 * H_ / 128, R_ / 128), thr, gsm>>>(xh, xl, wh, wl, nullptr, qkv,
                                                        R_, 3 * H_, H_, 0);
    conv_silu_kernel<<<R_ * H_ / 256, thr>>>(qkv, cq, qq, 3 * H_, 0);
    conv_silu_kernel<<<R_ * H_ / 256, thr>>>(qkv, ck, kk_, 3 * H_, H_);
    conv_silu_kernel<<<R_ * H_ / 256, thr>>>(qkv, cv, vv, 3 * H_, 2 * H_);
    wconv_kernel<<<dim3(MLPH_ / 32, GIN_ / 32), wb>>>(w1, w1h, w1l, GIN_, MLPH_);
    wconv_kernel<<<dim3(32, 32), wb>>>(Wo, woh, wol, H_, H_);
    precomp_kernel<<<B_ * NH_ * NCH_, thr,
                     (4 * 32 * RS + 2048) * sizeof(float)>>>();
    scan_kernel<<<128, 256, SC_SMEM>>>();
    fir_kernel<<<dim3(H_ / 64, B_ * L_ / 32), thr>>>(fsw, flw);
    gate_kernel<<<R_, thr>>>(x);
    split_kernel<<<(R_ * GIN_ + 255) / 256, thr>>>(gate, gh, gl, R_ * GIN_);
    gemm_bf<<<dim3(MLPH_ / 128, R_ / 128), thr, gsm>>>(gh, gl, w1h, w1l, b1, mlp,
                                                       R_, MLPH_, GIN_, 1);
    mlp2_kernel<<<R_, 128>>>(w2, b2);
    combine_kernel<<<R_, thr>>>(lt, onw);
    split_kernel<<<R_ * H_ / 256, thr>>>(oc, xh, xl, R_ * H_);
    gemm_bf<<<dim3(H_ / 128, R_ / 128), thr, gsm>>>(xh, xl, woh, wol, nullptr, out,
                                                    R_, H_, H_, 0);
}

// round 6
// speedup vs baseline: 3.7582x; 1.0382x over previous
#include <cuda_runtime.h>
#include <cuda_bf16.h>
#include <stdint.h>
#include <math.h>

#define B_   2
#define L_   2048
#define H_   1024
#define NH_  4
#define R_   (B_ * L_)       // 4096 rows
#define NCH_ 64              // chunks of 32 per sequence
#define GIN_ 1056
#define MLPH_ 2048

// ---------------- scratch ----------------
__device__ __align__(128) float g_qkv[(size_t)R_ * 3 * H_];
__device__ __align__(128) float g_qp[R_ * H_];     // u (fp32)
__device__ __align__(128) float g_vp[R_ * H_];     // delta_out
__device__ __align__(128) float g_q[R_ * H_];      // conv+silu q
__device__ __align__(128) float g_k[R_ * H_];      // conv+silu k
__device__ __align__(128) float g_v[R_ * H_];      // conv+silu v
__device__ __align__(128) float g_beta[R_ * NH_];
__device__ __align__(128) float g_fs[R_ * H_];
__device__ __align__(128) float g_fl[R_ * H_];
__device__ __align__(128) float g_mlp[(size_t)R_ * MLPH_];
__device__ __align__(128) float g_logits[R_ * 16];

// bf16 hi/lo tiles for the scan (emitted by precomp)
__device__ __align__(128) __nv_bfloat16 g_tqh[R_ * H_], g_tql[R_ * H_];
__device__ __align__(128) __nv_bfloat16 g_twh[R_ * H_], g_twl[R_ * H_];
__device__ __align__(128) __nv_bfloat16 g_tkth[(size_t)B_*NH_*NCH_*8192];
__device__ __align__(128) __nv_bfloat16 g_tktl[(size_t)B_*NH_*NCH_*8192];
__device__ __align__(128) __nv_bfloat16 g_tah[(size_t)B_*NH_*NCH_*1024];
__device__ __align__(128) __nv_bfloat16 g_tal[(size_t)B_*NH_*NCH_*1024];

// bf16 split weights [N][K] (QKV packed: 3072 x 1024)
__device__ __align__(128) __nv_bfloat16 g_wh[3 * H_ * H_], g_wl[3 * H_ * H_];
__device__ __align__(128) __nv_bfloat16 g_w1h[MLPH_ * GIN_], g_w1l[MLPH_ * GIN_];
__device__ __align__(128) __nv_bfloat16 g_woh[H_ * H_], g_wol[H_ * H_];
// bf16 split activations
__device__ __align__(128) __nv_bfloat16 g_xh[R_ * H_], g_xl[R_ * H_];   // x, later oc
__device__ __align__(128) __nv_bfloat16 g_gh[(size_t)R_ * GIN_], g_gl[(size_t)R_ * GIN_];

// ---------------- asm helpers ----------------
__device__ __forceinline__ void cpa16(uint32_t dst, const void* src) {
    asm volatile("cp.async.cg.shared.global [%0], [%1], 16;" :: "r"(dst), "l"(src));
}
#define CPA_COMMIT asm volatile("cp.async.commit_group;")
#define SMEMU32(p) ((uint32_t)__cvta_generic_to_shared(p))

#define MMA16816(d, a, b0, b1) \
  asm volatile("mma.sync.aligned.m16n8k16.row.col.f32.bf16.bf16.f32 " \
    "{%0,%1,%2,%3}, {%4,%5,%6,%7}, {%8,%9}, {%0,%1,%2,%3};" \
    : "+f"(d[0]), "+f"(d[1]), "+f"(d[2]), "+f"(d[3]) \
    : "r"(a[0]), "r"(a[1]), "r"(a[2]), "r"(a[3]), "r"(b0), "r"(b1))

#define LDSM4(r0, r1, r2, r3, addr) \
  asm volatile("ldmatrix.sync.aligned.m8n8.x4.shared.b16 {%0,%1,%2,%3}, [%4];" \
    : "=r"(r0), "=r"(r1), "=r"(r2), "=r"(r3) : "r"(addr))

// ---------------- elementwise fp32 -> bf16 hi/lo split ----------------
__global__ void split_kernel(const float* __restrict__ A,
                             __nv_bfloat16* __restrict__ Ah,
                             __nv_bfloat16* __restrict__ Al, int n)
{
    int i = blockIdx.x * 256 + threadIdx.x;
    if (i < n) {
        float v = A[i];
        __nv_bfloat16 h = __float2bfloat16(v);
        Ah[i] = h;
        Al[i] = __float2bfloat16(v - __bfloat162float(h));
    }
}

// ---------------- weight transpose + split ----------------
__global__ void wconv_kernel(const float* __restrict__ W,
                             __nv_bfloat16* __restrict__ Th,
                             __nv_bfloat16* __restrict__ Tl, int K, int N)
{
    __shared__ float t[32][33];
    int k0 = blockIdx.y * 32, n0 = blockIdx.x * 32;
    int tx = threadIdx.x, ty = threadIdx.y;
    for (int i = ty; i < 32; i += 8)
        t[i][tx] = W[(size_t)(k0 + i) * N + n0 + tx];
    __syncthreads();
    for (int i = ty; i < 32; i += 8) {
        float v = t[tx][i];
        __nv_bfloat16 hi = __float2bfloat16(v);
        __nv_bfloat16 lo = __float2bfloat16(v - __bfloat162float(hi));
        size_t o = (size_t)(n0 + i) * K + k0 + tx;
        Th[o] = hi; Tl[o] = lo;
    }
}

__global__ void wconv3_kernel(const float* __restrict__ Wq,
                              const float* __restrict__ Wk,
                              const float* __restrict__ Wv)
{
    __shared__ float t[32][33];
    int z = blockIdx.z;
    const float* W = (z == 0) ? Wq : (z == 1) ? Wk : Wv;
    int k0 = blockIdx.y * 32, n0 = blockIdx.x * 32;
    int tx = threadIdx.x, ty = threadIdx.y;
    for (int i = ty; i < 32; i += 8)
        t[i][tx] = W[(size_t)(k0 + i) * H_ + n0 + tx];
    __syncthreads();
    size_t base = (size_t)z * H_ * H_;
    for (int i = ty; i < 32; i += 8) {
        float v = t[tx][i];
        __nv_bfloat16 hi = __float2bfloat16(v);
        __nv_bfloat16 lo = __float2bfloat16(v - __bfloat162float(hi));
        size_t o = base + (size_t)(n0 + i) * H_ + k0 + tx;
        g_wh[o] = hi; g_wl[o] = lo;
    }
}

// ---------------- tensor-core GEMM, ldmatrix fragment loads ----------------
#define ASTR 40
#define STAGE_HALVES (4 * 128 * ASTR)

__global__ __launch_bounds__(256) void gemm_bf(
    const __nv_bfloat16* __restrict__ Ahg, const __nv_bfloat16* __restrict__ Alg,
    const __nv_bfloat16* __restrict__ Bhg, const __nv_bfloat16* __restrict__ Blg,
    const float* __restrict__ bias, float* __restrict__ C,
    int M, int N, int K, int act)
{
    extern __shared__ __nv_bfloat16 smh[];
    int tid = threadIdx.x;
    int row0 = blockIdx.y * 128, col0 = blockIdx.x * 128;
    int wid = tid >> 5, lane = tid & 31;
    int wm = (wid >> 1) * 32, wn = (wid & 1) * 64;
    int g = lane >> 2, t = lane & 3;
    int lr = lane & 7, seg = lane >> 3;   // ldmatrix lane mapping

    float acc[2][8][4];
#pragma unroll
    for (int i = 0; i < 2; i++)
#pragma unroll
        for (int j = 0; j < 8; j++)
#pragma unroll
            for (int q = 0; q < 4; q++) acc[i][j][q] = 0.f;

    const __nv_bfloat16* gsrc[4] = {Ahg, Alg, Bhg, Blg};
    int gr0[4] = {row0, row0, col0, col0};

    auto load_stage = [&](int s, int k0) {
        __nv_bfloat16* sp = smh + s * STAGE_HALVES;
#pragma unroll
        for (int a = 0; a < 4; a++) {
#pragma unroll
            for (int q = 0; q < 2; q++) {
                int c = tid * 2 + q;
                int r = c >> 2, sg = c & 3;
                uint32_t d = SMEMU32(sp + a * 128 * ASTR + r * ASTR + sg * 8);
                cpa16(d, gsrc[a] + (size_t)(gr0[a] + r) * K + k0 + sg * 8);
            }
        }
        CPA_COMMIT;
    };

    load_stage(0, 0);
    int nk = K / 32;
    for (int ki = 0; ki < nk; ki++) {
        if (ki + 1 < nk) {
            load_stage((ki + 1) & 1, (ki + 1) * 32);
            asm volatile("cp.async.wait_group 1;");
        } else {
            asm volatile("cp.async.wait_group 0;");
        }
        __syncthreads();
        __nv_bfloat16* sp = smh + (ki & 1) * STAGE_HALVES;
        __nv_bfloat16* Ah = sp;
        __nv_bfloat16* Al = sp + 128 * ASTR;
        __nv_bfloat16* Bh = sp + 2 * 128 * ASTR;
        __nv_bfloat16* Bl = sp + 3 * 128 * ASTR;
#pragma unroll
        for (int ks = 0; ks < 2; ks++) {
            int ko = ks * 16;
            int arow = wm + lr + ((seg & 1) << 3);
            int acol = ko + ((seg >> 1) << 3);
            uint32_t afh[2][4], afl[2][4];
#pragma unroll
            for (int mi = 0; mi < 2; mi++) {
                LDSM4(afh[mi][0], afh[mi][1], afh[mi][2], afh[mi][3],
                      SMEMU32(&Ah[(arow + mi * 16) * ASTR + acol]));
                LDSM4(afl[mi][0], afl[mi][1], afl[mi][2], afl[mi][3],
                      SMEMU32(&Al[(arow + mi * 16) * ASTR + acol]));
            }
            int brow = wn + lr + ((seg >> 1) << 3);
            int bcol = ko + ((seg & 1) << 3);
#pragma unroll
            for (int nip = 0; nip < 4; nip++) {
                uint32_t bh4[4], bl4[4];
                LDSM4(bh4[0], bh4[1], bh4[2], bh4[3],
                      SMEMU32(&Bh[(brow + nip * 16) * ASTR + bcol]));
                LDSM4(bl4[0], bl4[1], bl4[2], bl4[3],
                      SMEMU32(&Bl[(brow + nip * 16) * ASTR + bcol]));
#pragma unroll
                for (int sub = 0; sub < 2; sub++) {
                    int ni = nip * 2 + sub;
                    uint32_t bh0 = bh4[sub * 2], bh1 = bh4[sub * 2 + 1];
                    uint32_t bl0 = bl4[sub * 2], bl1 = bl4[sub * 2 + 1];
#pragma unroll
                    for (int mi = 0; mi < 2; mi++) {
                        MMA16816(acc[mi][ni], afh[mi], bh0, bh1);
                        MMA16816(acc[mi][ni], afl[mi], bh0, bh1);
                        MMA16816(acc[mi][ni], afh[mi], bl0, bl1);
                    }
                }
            }
        }
        __syncthreads();
    }

#pragma unroll
    for (int mi = 0; mi < 2; mi++)
#pragma unroll
        for (int ni = 0; ni < 8; ni++) {
            int r = row0 + wm + mi * 16 + g;
            int c = col0 + wn + ni * 8 + 2 * t;
            float v[4];
#pragma unroll
            for (int q = 0; q < 4; q++) {
                float x = acc[mi][ni][q];
                if (bias) x += bias[c + (q & 1)];
                if (act == 1) x = 0.5f * x * (1.f + erff(x * 0.70710678118654752f));
                v[q] = x;
            }
            *(float2*)(C + (size_t)r * N + c)       = make_float2(v[0], v[1]);
            *(float2*)(C + (size_t)(r + 8) * N + c) = make_float2(v[2], v[3]);
        }
}

// ---------------- beta ----------------
__global__ void beta_kernel(const float* __restrict__ x, const float* __restrict__ Wb)
{
    int r = blockIdx.x * 4 + (threadIdx.x >> 5);
    int lane = threadIdx.x & 31;
    float acc0 = 0, acc1 = 0, acc2 = 0, acc3 = 0;
    const float* xr = x + (size_t)r * H_;
    for (int kk = lane; kk < H_; kk += 32) {
        float xv = xr[kk];
        const float* w = Wb + kk * 4;
        acc0 += xv * w[0]; acc1 += xv * w[1]; acc2 += xv * w[2]; acc3 += xv * w[3];
    }
#pragma unroll
    for (int off = 16; off; off >>= 1) {
        acc0 += __shfl_down_sync(~0u, acc0, off);
        acc1 += __shfl_down_sync(~0u, acc1, off);
        acc2 += __shfl_down_sync(~0u, acc2, off);
        acc3 += __shfl_down_sync(~0u, acc3, off);
    }
    if (lane == 0) {
        g_beta[r * 4 + 0] = 1.f / (1.f + expf(-acc0));
        g_beta[r * 4 + 1] = 1.f / (1.f + expf(-acc1));
        g_beta[r * 4 + 2] = 1.f / (1.f + expf(-acc2));
        g_beta[r * 4 + 3] = 1.f / (1.f + expf(-acc3));
    }
}

// ---------------- fused causal conv K=4 + silu (q,k,v in one launch) ----------------
__global__ void conv3_kernel(const float* __restrict__ cq,
                             const float* __restrict__ ck,
                             const float* __restrict__ cv)
{
    int z = blockIdx.y;
    const float* w = (z == 0) ? cq : (z == 1) ? ck : cv;
    float* dst = (z == 0) ? g_q : (z == 1) ? g_k : g_v;
    int srcOff = z * H_;

    int tid = blockIdx.x * blockDim.x + threadIdx.x;
    int c = tid & (H_ - 1);
    int r = tid >> 10;
    int b = r >> 11;
    int l = r & (L_ - 1);
    const float* wc = w + c * 4;
    float acc = 0.f;
#pragma unroll
    for (int j = 0; j < 4; j++) {
        int ll = l - 3 + j;
        if (ll >= 0) acc += g_qkv[(size_t)(b * L_ + ll) * 3 * H_ + srcOff + c] * wc[j];
    }
    dst[tid] = acc / (1.f + expf(-acc));
}

// ---------------- delta precompute: emits bf16 hi/lo tiles ----------------
#define RS 257
__global__ __launch_bounds__(256) void precomp_kernel()
{
    extern __shared__ float sm[];
    float* Qs = sm;
    float* Ks = Qs + 32 * RS;
    float* KB = Ks + 32 * RS;
    float* VB = KB + 32 * RS;
    float* Am = VB + 32 * RS;
    float* Tm = Am + 1024;
    __shared__ float rbeta[32], qn_s[32], kn_s[32];

    int bhn = blockIdx.x;
    int n = bhn % NCH_; int bh = bhn / NCH_;
    int b = bh >> 2, h = bh & 3;
    int l0 = n * 32;
    int tid = threadIdx.x, wi = tid >> 5, lane = tid & 31;

    for (int e = tid; e < 8192; e += 256) {
        int i = e >> 8, d = e & 255;
        size_t gi = ((size_t)(b * L_ + l0 + i) << 10) + h * 256 + d;
        Qs[i * RS + d] = g_q[gi];
        Ks[i * RS + d] = g_k[gi];
    }
    if (tid < 32) rbeta[tid] = g_beta[(b * L_ + l0 + tid) * 4 + h];
    __syncthreads();

    for (int rr = wi; rr < 32; rr += 8) {
        float sq = 0, sk = 0;
        for (int d = lane; d < 256; d += 32) {
            float a = Qs[rr * RS + d]; sq += a * a;
            float c = Ks[rr * RS + d]; sk += c * c;
        }
#pragma unroll
        for (int off = 16; off; off >>= 1) {
            sq += __shfl_down_sync(~0u, sq, off);
            sk += __shfl_down_sync(~0u, sk, off);
        }
        if (lane == 0) { qn_s[rr] = rsqrtf(sq + 1e-6f); kn_s[rr] = rsqrtf(sk + 1e-6f); }
    }
    __syncthreads();

    for (int e = tid; e < 8192; e += 256) {
        int i = e >> 8, d = e & 255;
        size_t gi = ((size_t)(b * L_ + l0 + i) << 10) + h * 256 + d;
        float qv = Qs[i * RS + d] * qn_s[i]; Qs[i * RS + d] = qv;
        float kv = Ks[i * RS + d] * kn_s[i]; Ks[i * RS + d] = kv;
        KB[i * RS + d] = kv * rbeta[i];
        VB[i * RS + d] = g_v[gi] * rbeta[i];
        __nv_bfloat16 qh = __float2bfloat16(qv);
        g_tqh[gi] = qh;
        g_tql[gi] = __float2bfloat16(qv - __bfloat162float(qh));
    }
    __syncthreads();

    {
        size_t ckb = ((size_t)bh * NCH_ + n) * 8192;
        for (int e = tid; e < 8192; e += 256) {
            int d = e >> 5, i = e & 31;
            float kv = Ks[i * RS + d];
            __nv_bfloat16 kh = __float2bfloat16(kv);
            g_tkth[ckb + e] = kh;
            g_tktl[ckb + e] = __float2bfloat16(kv - __bfloat162float(kh));
        }
    }

    for (int e = tid; e < 1024; e += 256) {
        int i = e >> 5, j = e & 31;
        float s = 0.f;
        if (j < i) {
            const float* a = KB + i * RS; const float* c = Ks + j * RS;
            for (int d = 0; d < 256; d++) s += a[d] * c[d];
        }
        Am[e] = s;
    }
    __syncthreads();

    if (wi == 0) {
        int j = lane;
        for (int i = 0; i < 32; i++) {
            float val = (i == j) ? 1.f : 0.f;
            for (int m = j; m < i; m++) val -= Am[i * 32 + m] * Tm[m * 32 + j];
            Tm[i * 32 + j] = val;
            __syncwarp();
        }
    }
    __syncthreads();

    {
        size_t ab = ((size_t)bh * NCH_ + n) * 1024;
        for (int e = tid; e < 1024; e += 256) {
            int i = e >> 5, j = e & 31;
            float s = 0.f;
            if (j <= i) {
                const float* a = Qs + i * RS; const float* c = Ks + j * RS;
                for (int d = 0; d < 256; d++) s += a[d] * c[d];
            }
            __nv_bfloat16 hv = __float2bfloat16(s);
            g_tah[ab + e] = hv;
            g_tal[ab + e] = __float2bfloat16(s - __bfloat162float(hv));
        }
    }

    for (int e = tid; e < 8192; e += 256) {
        int i = e >> 8, d = e & 255;
        float su = 0, sw = 0;
        const float* tr = Tm + i * 32;
#pragma unroll
        for (int m = 0; m < 32; m++) {
            float t = tr[m];
            su += t * VB[m * RS + d];
            sw += t * KB[m * RS + d];
        }
        size_t gi = ((size_t)(b * L_ + l0 + i) << 10) + h * 256 + d;
        g_qp[gi] = su;
        __nv_bfloat16 wh_ = __float2bfloat16(sw);
        g_twh[gi] = wh_;
        g_twl[gi] = __float2bfloat16(sw - __bfloat162float(wh_));
    }
}

// ---------------- tensor-core scan (validated round-5 version) ----------------
#define SC_SMEM 228352
#define STG_OFF 78848
#define STG_SZ  74752

__global__ __launch_bounds__(256) void scan_kernel()
{
    extern __shared__ char sc[];
    float* S  = (float*)sc;
    float* U2 = (float*)(sc + 16384);
    __nv_bfloat16* SbTh = (__nv_bfloat16*)(sc + 18432);
    __nv_bfloat16* SbTl = (__nv_bfloat16*)(sc + 26880);
    __nv_bfloat16* U2Th = (__nv_bfloat16*)(sc + 35328);
    __nv_bfloat16* U2Tl = (__nv_bfloat16*)(sc + 36608);
    __nv_bfloat16* KTh  = (__nv_bfloat16*)(sc + 37888);
    __nv_bfloat16* KTl  = (__nv_bfloat16*)(sc + 58368);

    int blk = blockIdx.x;
    int bh = blk >> 4, slice = blk & 15;
    int b = bh >> 2, h = bh & 3;
    int tid = threadIdx.x;
    int wi = tid >> 5, lane = tid & 31;
    int g = lane >> 2, t4 = lane & 3;
    int dvb = h * 256 + slice * 16;

    for (int e = tid; e < 4096; e += 256) S[e] = 0.f;
    for (int e = tid; e < 16 * 264; e += 256) {
        SbTh[e] = __float2bfloat16(0.f);
        SbTl[e] = __float2bfloat16(0.f);
    }

    auto issue_main = [&](int n, int buf) {
        char* sp = sc + STG_OFF + buf * STG_SZ;
        __nv_bfloat16* dsts[4] = {
            (__nv_bfloat16*)sp, (__nv_bfloat16*)(sp + 16896),
            (__nv_bfloat16*)(sp + 33792), (__nv_bfloat16*)(sp + 50688)};
        const __nv_bfloat16* srcs[4] = {g_twh, g_twl, g_tqh, g_tql};
        int row0 = b * L_ + n * 32;
#pragma unroll
        for (int it = 0; it < 16; it++) {
            int c = tid + it * 256;
            int a = c >> 10, rem = c & 1023;
            int r = rem >> 5, s = rem & 31;
            cpa16(SMEMU32(dsts[a] + r * 264 + s * 8),
                  srcs[a] + ((size_t)(row0 + r) << 10) + h * 256 + s * 8);
        }
        if (tid < 128) {
            int r = tid >> 2, s = tid & 3;
            float* Uf = (float*)(sp + 67584);
            cpa16(SMEMU32(Uf + r * 16 + s * 4),
                  g_qp + ((size_t)(row0 + r) << 10) + dvb + s * 4);
        }
        {
            int a = tid >> 7, rem = tid & 127;
            int r = rem >> 2, s = rem & 3;
            __nv_bfloat16* dst = (__nv_bfloat16*)(sp + (a ? 72192 : 69632));
            const __nv_bfloat16* src = a ? g_tal : g_tah;
            cpa16(SMEMU32(dst + r * 40 + s * 8),
                  src + ((size_t)bh * NCH_ + n) * 1024 + r * 32 + s * 8);
        }
        CPA_COMMIT;
    };

    auto issue_kT = [&](int n) {
        size_t base = ((size_t)bh * NCH_ + n) * 8192;
#pragma unroll
        for (int it = 0; it < 8; it++) {
            int c = tid + it * 256;
            int a = c >> 10, rem = c & 1023;
            int r = rem >> 2, s = rem & 3;
            __nv_bfloat16* dst = a ? KTl : KTh;
            const __nv_bfloat16* src = a ? g_tktl : g_tkth;
            cpa16(SMEMU32(dst + r * 40 + s * 8), src + base + r * 32 + s * 8);
        }
        CPA_COMMIT;
    };

    issue_main(0, 0);
    issue_kT(0);
    int buf = 0;

#pragma unroll 1
    for (int n = 0; n < NCH_; n++) {
        asm volatile("cp.async.wait_group 0;");
        if (n + 1 < NCH_) issue_main(n + 1, buf ^ 1);
        __syncthreads();

        char* sp = sc + STG_OFF + buf * STG_SZ;
        const __nv_bfloat16* Wh = (const __nv_bfloat16*)sp;
        const __nv_bfloat16* Wl = (const __nv_bfloat16*)(sp + 16896);
        const __nv_bfloat16* Qh = (const __nv_bfloat16*)(sp + 33792);
        const __nv_bfloat16* Ql = (const __nv_bfloat16*)(sp + 50688);
        const float* Uf = (const float*)(sp + 67584);
        const __nv_bfloat16* Ath = (const __nv_bfloat16*)(sp + 69632);
        const __nv_bfloat16* Atl = (const __nv_bfloat16*)(sp + 72192);

        float c0[4] = {0,0,0,0}, c1[4] = {0,0,0,0}, c2[4] = {0,0,0,0};
        int w4 = wi & 3;
        int m0 = (w4 >> 1) * 16, n0 = (w4 & 1) * 8;
        const __nv_bfloat16* Ah = (wi < 4) ? Wh : Qh;
        const __nv_bfloat16* Al = (wi < 4) ? Wl : Ql;
#pragma unroll
        for (int kk = 0; kk < 16; kk++) {
            int ka = kk * 16 + 2 * t4;
            uint32_t ah[4], al[4];
            ah[0] = *(const uint32_t*)&Ah[(m0 + g) * 264 + ka];
            ah[1] = *(const uint32_t*)&Ah[(m0 + 8 + g) * 264 + ka];
            ah[2] = *(const uint32_t*)&Ah[(m0 + g) * 264 + ka + 8];
            ah[3] = *(const uint32_t*)&Ah[(m0 + 8 + g) * 264 + ka + 8];
            al[0] = *(const uint32_t*)&Al[(m0 + g) * 264 + ka];
            al[1] = *(const uint32_t*)&Al[(m0 + 8 + g) * 264 + ka];
            al[2] = *(const uint32_t*)&Al[(m0 + g) * 264 + ka + 8];
            al[3] = *(const uint32_t*)&Al[(m0 + 8 + g) * 264 + ka + 8];
            uint32_t bh0 = *(const uint32_t*)&SbTh[(n0 + g) * 264 + ka];
            uint32_t bh1 = *(const uint32_t*)&SbTh[(n0 + g) * 264 + ka + 8];
            uint32_t bl0 = *(const uint32_t*)&SbTl[(n0 + g) * 264 + ka];
            uint32_t bl1 = *(const uint32_t*)&SbTl[(n0 + g) * 264 + ka + 8];
            MMA16816(c0, ah, bh0, bh1);
            MMA16816(c1, al, bh0, bh1);
            MMA16816(c2, ah, bl0, bl1);
        }
        if (wi < 4) {
            U2[(m0 + g) * 16 + n0 + 2 * t4]         = Uf[(m0 + g) * 16 + n0 + 2 * t4]         - (c0[0] + c1[0] + c2[0]);
            U2[(m0 + g) * 16 + n0 + 2 * t4 + 1]     = Uf[(m0 + g) * 16 + n0 + 2 * t4 + 1]     - (c0[1] + c1[1] + c2[1]);
            U2[(m0 + 8 + g) * 16 + n0 + 2 * t4]     = Uf[(m0 + 8 + g) * 16 + n0 + 2 * t4]     - (c0[2] + c1[2] + c2[2]);
            U2[(m0 + 8 + g) * 16 + n0 + 2 * t4 + 1] = Uf[(m0 + 8 + g) * 16 + n0 + 2 * t4 + 1] - (c0[3] + c1[3] + c2[3]);
        }
        __syncthreads();

#pragma unroll
        for (int q2 = 0; q2 < 2; q2++) {
            int e = tid + q2 * 256;
            int i2 = e >> 4, j2 = e & 15;
            float v = U2[i2 * 16 + j2];
            __nv_bfloat16 hv = __float2bfloat16(v);
            U2Th[j2 * 40 + i2] = hv;
            U2Tl[j2 * 40 + i2] = __float2bfloat16(v - __bfloat162float(hv));
        }
        __syncthreads();

        if (wi >= 4) {
#pragma unroll
            for (int kk = 0; kk < 2; kk++) {
                int ka = kk * 16 + 2 * t4;
                uint32_t ah[4], al[4];
                ah[0] = *(const uint32_t*)&Ath[(m0 + g) * 40 + ka];
                ah[1] = *(const uint32_t*)&Ath[(m0 + 8 + g) * 40 + ka];
                ah[2] = *(const uint32_t*)&Ath[(m0 + g) * 40 + ka + 8];
                ah[3] = *(const uint32_t*)&Ath[(m0 + 8 + g) * 40 + ka + 8];
                al[0] = *(const uint32_t*)&Atl[(m0 + g) * 40 + ka];
                al[1] = *(const uint32_t*)&Atl[(m0 + 8 + g) * 40 + ka];
                al[2] = *(const uint32_t*)&Atl[(m0 + g) * 40 + ka + 8];
                al[3] = *(const uint32_t*)&Atl[(m0 + 8 + g) * 40 + ka + 8];
                uint32_t bh0 = *(const uint32_t*)&U2Th[(n0 + g) * 40 + ka];
                uint32_t bh1 = *(const uint32_t*)&U2Th[(n0 + g) * 40 + ka + 8];
                uint32_t bl0 = *(const uint32_t*)&U2Tl[(n0 + g) * 40 + ka];
                uint32_t bl1 = *(const uint32_t*)&U2Tl[(n0 + g) * 40 + ka + 8];
                MMA16816(c0, ah, bh0, bh1);
                MMA16816(c1, al, bh0, bh1);
                MMA16816(c2, ah, bl0, bl1);
            }
            size_t ob = ((size_t)(b * L_ + n * 32) << 10) + dvb + n0 + 2 * t4;
            *(float2*)(g_vp + ob + ((size_t)(m0 + g) << 10)) =
                make_float2(c0[0] + c1[0] + c2[0], c0[1] + c1[1] + c2[1]);
            *(float2*)(g_vp + ob + ((size_t)(m0 + 8 + g) << 10)) =
                make_float2(c0[2] + c1[2] + c2[2], c0[3] + c1[3] + c2[3]);
        }

#pragma unroll
        for (int mm = 0; mm < 2; mm++)
#pragma unroll
        for (int nn = 0; nn < 2; nn++) {
            int m0p = (wi * 2 + mm) * 16, n0p = nn * 8;
            float d0[4];
            float2 s01 = *(float2*)(S + (m0p + g) * 16 + n0p + 2 * t4);
            float2 s23 = *(float2*)(S + (m0p + 8 + g) * 16 + n0p + 2 * t4);
            d0[0] = s01.x; d0[1] = s01.y; d0[2] = s23.x; d0[3] = s23.y;
#pragma unroll
            for (int kk = 0; kk < 2; kk++) {
                int ka = kk * 16 + 2 * t4;
                uint32_t ah[4], al[4];
                ah[0] = *(const uint32_t*)&KTh[(m0p + g) * 40 + ka];
                ah[1] = *(const uint32_t*)&KTh[(m0p + 8 + g) * 40 + ka];
                ah[2] = *(const uint32_t*)&KTh[(m0p + g) * 40 + ka + 8];
                ah[3] = *(const uint32_t*)&KTh[(m0p + 8 + g) * 40 + ka + 8];
                al[0] = *(const uint32_t*)&KTl[(m0p + g) * 40 + ka];
                al[1] = *(const uint32_t*)&KTl[(m0p + 8 + g) * 40 + ka];
                al[2] = *(const uint32_t*)&KTl[(m0p + g) * 40 + ka + 8];
                al[3] = *(const uint32_t*)&KTl[(m0p + 8 + g) * 40 + ka + 8];
                uint32_t bh0 = *(const uint32_t*)&U2Th[(n0p + g) * 40 + ka];
                uint32_t bh1 = *(const uint32_t*)&U2Th[(n0p + g) * 40 + ka + 8];
                uint32_t bl0 = *(const uint32_t*)&U2Tl[(n0p + g) * 40 + ka];
                uint32_t bl1 = *(const uint32_t*)&U2Tl[(n0p + g) * 40 + ka + 8];
                MMA16816(d0, ah, bh0, bh1);
                MMA16816(d0, al, bh0, bh1);
                MMA16816(d0, ah, bl0, bl1);
            }
            *(float2*)(S + (m0p + g) * 16 + n0p + 2 * t4)     = make_float2(d0[0], d0[1]);
            *(float2*)(S + (m0p + 8 + g) * 16 + n0p + 2 * t4) = make_float2(d0[2], d0[3]);
        }
        __syncthreads();

        if (n + 1 < NCH_) issue_kT(n + 1);

        {
            int k = tid;
#pragma unroll
            for (int j = 0; j < 16; j++) {
                float v = S[k * 16 + j];
                __nv_bfloat16 hv = __float2bfloat16(v);
                SbTh[j * 264 + k] = hv;
                SbTl[j * 264 + k] = __float2bfloat16(v - __bfloat162float(hv));
            }
        }
        __syncthreads();
        buf ^= 1;
    }
}

// ---------------- FIR convs ----------------
__global__ __launch_bounds__(256) void fir_kernel(const float* __restrict__ ws,
                                                  const float* __restrict__ wl)
{
    __shared__ float vt[94][64];
    __shared__ float wls[64 * 63];
    __shared__ float wss[64 * 3];
    int cb = blockIdx.x;
    int lb = blockIdx.y;
    int b = lb >> 6;
    int l0 = (lb & 63) * 32;
    int c0 = cb * 64;
    int tid = threadIdx.x;

    for (int e = tid; e < 94 * 64; e += 256) {
        int rr = e >> 6, cc = e & 63;
        int l = l0 - 62 + rr;
        vt[rr][cc] = (l >= 0) ? g_v[((size_t)(b * L_ + l) << 10) + c0 + cc] : 0.f;
    }
    for (int e = tid; e < 64 * 63; e += 256) wls[e] = wl[(size_t)c0 * 63 + e];
    for (int e = tid; e < 64 * 3; e += 256)  wss[e] = ws[(size_t)c0 * 3 + e];
    __syncthreads();

    for (int e = tid; e < 32 * 64; e += 256) {
        int i = e >> 6, cc = e & 63;
        float aL = 0.f, aS = 0.f;
        const float* wlr = wls + cc * 63;
#pragma unroll 9
        for (int j = 0; j < 63; j++) aL += vt[i + j][cc] * wlr[j];
        const float* wsr = wss + cc * 3;
#pragma unroll
        for (int j = 0; j < 3; j++) aS += vt[i + 60 + j][cc] * wsr[j];
        size_t gi = ((size_t)(b * L_ + l0 + i) << 10) + c0 + cc;
        g_fl[gi] = aL;
        g_fs[gi] = aS;
    }
}

// ---------------- gate input: write bf16 hi/lo directly ----------------
__global__ void gate_kernel(const float* __restrict__ x)
{
    __shared__ float stats[32];
    int r = blockIdx.x, tid = threadIdx.x;
    int wi = tid >> 5, lane = tid & 31;
    for (int p = wi; p < 16; p += 8) {
        int br = p >> 2, h = p & 3;
        const float* src = (br == 0 ? g_fs : br == 1 ? g_fl : br == 2 ? g_vp : g_v)
                           + ((size_t)r << 10) + h * 256;
        float s = 0, s2 = 0;
        for (int d = lane; d < 256; d += 32) { float t = src[d]; s += t; s2 += t * t; }
#pragma unroll
        for (int off = 16; off; off >>= 1) {
            s += __shfl_down_sync(~0u, s, off);
            s2 += __shfl_down_sync(~0u, s2, off);
        }
        if (lane == 0) {
            float mean = s * (1.f / 256.f);
            float var = s2 * (1.f / 256.f) - mean * mean;
            stats[br * 8 + h] = mean;
            stats[br * 8 + 4 + h] = sqrtf(fmaxf(var, 1e-6f));
        }
    }
    __syncthreads();
    const float* xr = x + (size_t)r * H_;
    size_t gb = (size_t)r * GIN_;
    for (int e = tid; e < GIN_; e += 256) {
        float v = (e < H_) ? xr[e] : stats[e - H_];
        __nv_bfloat16 h = __float2bfloat16(v);
        g_gh[gb + e] = h;
        g_gl[gb + e] = __float2bfloat16(v - __bfloat162float(h));
    }
}

// ---------------- MLP2 ----------------
__global__ void mlp2_kernel(const float* __restrict__ w2, const float* __restrict__ b2)
{
    int r = blockIdx.x, tid = threadIdx.x;
    float acc[16];
#pragma unroll
    for (int o = 0; o < 16; o++) acc[o] = 0.f;
    const float* hr = g_mlp + (size_t)r * MLPH_;
    for (int kk = tid; kk < MLPH_; kk += 128) {
        float hv = hr[kk];
        const float4* wr = (const float4*)(w2 + (size_t)kk * 16);
        float4 w0 = wr[0], w1 = wr[1], w2v = wr[2], w3 = wr[3];
        acc[0] += hv * w0.x; acc[1] += hv * w0.y; acc[2] += hv * w0.z; acc[3] += hv * w0.w;
        acc[4] += hv * w1.x; acc[5] += hv * w1.y; acc[6] += hv * w1.z; acc[7] += hv * w1.w;
        acc[8] += hv * w2v.x; acc[9] += hv * w2v.y; acc[10] += hv * w2v.z; acc[11] += hv * w2v.w;
        acc[12] += hv * w3.x; acc[13] += hv * w3.y; acc[14] += hv * w3.z; acc[15] += hv * w3.w;
    }
    __shared__ float part[4][16];
    int wi = tid >> 5, lane = tid & 31;
#pragma unroll
    for (int o = 0; o < 16; o++) {
        float v = acc[o];
#pragma unroll
        for (int off = 16; off; off >>= 1) v += __shfl_down_sync(~0u, v, off);
        if (lane == 0) part[wi][o] = v;
    }
    __syncthreads();
    if (tid < 16)
        g_logits[r * 16 + tid] =
            part[0][tid] + part[1][tid] + part[2][tid] + part[3][tid] + b2[tid];
}

// ---------------- combine + RMSNorm: write oc hi/lo directly ----------------
__global__ void combine_kernel(const float* __restrict__ ltemp,
                               const float* __restrict__ onw)
{
    int r = blockIdx.x, tid = threadIdx.x;
    __shared__ float red[256];
    const float* lg = g_logits + r * 16;
#pragma unroll 1
    for (int h = 0; h < 4; h++) {
        float temp = log1pf(expf(ltemp[h])) + 1e-4f;
        float l0 = lg[h * 4 + 0] / temp, l1 = lg[h * 4 + 1] / temp;
        float l2 = lg[h * 4 + 2] / temp, l3 = lg[h * 4 + 3] / temp;
        float mx = fmaxf(fmaxf(l0, l1), fmaxf(l2, l3));
        float e0 = expf(l0 - mx), e1 = expf(l1 - mx), e2 = expf(l2 - mx), e3 = expf(l3 - mx);
        float inv = 1.f / (e0 + e1 + e2 + e3);
        size_t idx = ((size_t)r << 10) + h * 256 + tid;
        float ov = (e0 * g_fs[idx] + e1 * g_fl[idx] + e2 * g_vp[idx] + e3 * g_v[idx]) * inv;
        red[tid] = ov * ov;
        __syncthreads();
        for (int s = 128; s; s >>= 1) { if (tid < s) red[tid] += red[tid + s]; __syncthreads(); }
        float scale = rsqrtf(red[0] * (1.f / 256.f) + 1e-5f);
        float val = ov * scale * onw[tid];
        __nv_bfloat16 hv = __float2bfloat16(val);
        g_xh[idx] = hv;
        g_xl[idx] = __float2bfloat16(val - __bfloat162float(hv));
        __syncthreads();
    }
}

// ---------------- launch ----------------
extern "C" void kernel_launch(void* const* d_in, const int* in_sizes, int n_in,
                              void* d_out, int out_size)
{
    const float* x   = (const float*)d_in[0];
    const float* Wq  = (const float*)d_in[1];
    const float* Wk  = (const float*)d_in[2];
    const float* Wv  = (const float*)d_in[3];
    const float* Wb  = (const float*)d_in[4];
    const float* cq  = (const float*)d_in[5];
    const float* ck  = (const float*)d_in[6];
    const float* cv  = (const float*)d_in[7];
    const float* fsw = (const float*)d_in[8];
    const float* flw = (const float*)d_in[9];
    const float* w1  = (const float*)d_in[10];
    const float* b1  = (const float*)d_in[11];
    const float* w2  = (const float*)d_in[12];
    const float* b2  = (const float*)d_in[13];
    const float* lt  = (const float*)d_in[14];
    const float* onw = (const float*)d_in[15];
    const float* Wo  = (const float*)d_in[16];
    float* out = (float*)d_out;

    void* p;
    float *qkv, *mlp;
    __nv_bfloat16 *wh, *wl, *w1h, *w1l, *woh, *wol, *xh, *xl, *gh, *gl;
    cudaGetSymbolAddress(&p, g_qkv); qkv = (float*)p;
    cudaGetSymbolAddress(&p, g_mlp); mlp = (float*)p;
    cudaGetSymbolAddress(&p, g_wh);  wh = (__nv_bfloat16*)p;
    cudaGetSymbolAddress(&p, g_wl);  wl = (__nv_bfloat16*)p;
    cudaGetSymbolAddress(&p, g_w1h); w1h = (__nv_bfloat16*)p;
    cudaGetSymbolAddress(&p, g_w1l); w1l = (__nv_bfloat16*)p;
    cudaGetSymbolAddress(&p, g_woh); woh = (__nv_bfloat16*)p;
    cudaGetSymbolAddress(&p, g_wol); wol = (__nv_bfloat16*)p;
    cudaGetSymbolAddress(&p, g_xh);  xh = (__nv_bfloat16*)p;
    cudaGetSymbolAddress(&p, g_xl);  xl = (__nv_bfloat16*)p;
    cudaGetSymbolAddress(&p, g_gh);  gh = (__nv_bfloat16*)p;
    cudaGetSymbolAddress(&p, g_gl);  gl = (__nv_bfloat16*)p;

    static int attr_done = 0;
    if (!attr_done) {
        cudaFuncSetAttribute(gemm_bf, cudaFuncAttributeMaxDynamicSharedMemorySize,
                             2 * STAGE_HALVES * (int)sizeof(__nv_bfloat16));
        cudaFuncSetAttribute(precomp_kernel, cudaFuncAttributeMaxDynamicSharedMemorySize,
                             (4 * 32 * RS + 2048) * (int)sizeof(float));
        cudaFuncSetAttribute(scan_kernel, cudaFuncAttributeMaxDynamicSharedMemorySize,
                             SC_SMEM);
        attr_done = 1;
    }

    dim3 thr(256);
    dim3 wb(32, 8);
    int gsm = 2 * STAGE_HALVES * (int)sizeof(__nv_bfloat16);

    split_kernel<<<R_ * H_ / 256, thr>>>(x, xh, xl, R_ * H_);
    wconv3_kernel<<<dim3(32, 32, 3), wb>>>(Wq, Wk, Wv);
    beta_kernel<<<R_ / 4, 128>>>(x, Wb);
    gemm_bf<<<dim3(3 * H_ / 128, R_ / 128), thr, gsm>>>(xh, xl, wh, wl, nullptr, qkv,
                                                        R_, 3 * H_, H_, 0);
    conv3_kernel<<<dim3(R_ * H_ / 256, 3), thr>>>(cq, ck, cv);
    wconv_kernel<<<dim3(MLPH_ / 32, GIN_ / 32), wb>>>(w1, w1h, w1l, GIN_, MLPH_);
    wconv_kernel<<<dim3(32, 32), wb>>>(Wo, woh, wol, H_, H_);
    precomp_kernel<<<B_ * NH_ * NCH_, thr,
                     (4 * 32 * RS + 2048) * sizeof(float)>>>();
    scan_kernel<<<128, 256, SC_SMEM>>>();
    fir_kernel<<<dim3(H_ / 64, B_ * L_ / 32), thr>>>(fsw, flw);
    gate_kernel<<<R_, thr>>>(x);
    gemm_bf<<<dim3(MLPH_ / 128, R_ / 128), thr, gsm>>>(gh, gl, w1h, w1l, b1, mlp,
                                                       R_, MLPH_, GIN_, 1);
    mlp2_kernel<<<R_, 128>>>(w2, b2);
    combine_kernel<<<R_, thr>>>(lt, onw);
    gemm_bf<<<dim3(H_ / 128, R_ / 128), thr, gsm>>>(xh, xl, woh, wol, nullptr, out,
                                                    R_, H_, H_, 0);
}